// round 14
// baseline (speedup 1.0000x reference)
#include <cuda_runtime.h>
#include <cuda_fp16.h>
#include <math.h>
#include <stdint.h>

// ---------------- problem constants ----------------
#define DIMC   384
#define HEADS  6
#define HD     64
#define HIDDEN 1536
#define BATCH  4
#define NX     2048
#define NY     256
#define MTOK   2304
#define TTOK   (BATCH*MTOK)          // 9216
#define QKVN   (3*DIMC)              // 1152
#define ATT_SCALE 0.125f
#define LN_EPS 1e-5f

#define HTS 72                       // half row stride (elements); 144B = 36 u32

// attention smem: K/V double buffers only
#define SMEM_ATTN5 (4*64*HTS*2)      // 36,864 B

// GEMM smem: A/W tiles 128x64 halves, double buffered
#define GT_BYTES (128*HTS*2)         // 18,432 per tile buffer
#define SMEM_GEMM (4*GT_BYTES)       // 73,728 B

// unified attention work decomposition
#define SSPLIT 2                     // self-attn K splits (1024 keys each)
#define CSPLIT 4                     // cross-attn K splits (576 keys each)
#define SQB    (NX/128)              // 16 self q-blocks
#define CQB    (NY/128)              // 2 cross q-blocks
#define QBLKS  (SQB + CQB)           // 18 q-blocks total
#define ITEMS  (SQB*SSPLIT + CQB*CSPLIT)   // 40 work items per (h,b)

// weight scratch offsets (half weights)
#define OFF_QKVW 0
#define OFF_PROJW (QKVN*DIMC)
#define OFF_FC1W  (OFF_PROJW + DIMC*DIMC)
#define OFF_FC2W  (OFF_FC1W + HIDDEN*DIMC)
#define W_TOTAL   (OFF_FC2W + DIMC*HIDDEN)

// ---------------- scratch ----------------
__device__ __half g_catln[TTOK*DIMC];
__device__ __half g_qkvh [TTOK*QKVN];
__device__ __half g_attno[TTOK*DIMC];
__device__ __half g_ln2  [TTOK*DIMC];
__device__ __half g_fc1  [TTOK*HIDDEN];
__device__ __half g_wrnd [W_TOTAL];
__device__ float  g_pO   [BATCH*HEADS*QBLKS*4*128*64];   // 56.6 MB partial O
__device__ float  g_pL   [BATCH*HEADS*QBLKS*4*128];

// ---------------- helpers ----------------
__device__ __forceinline__ void cp16(void* smem, const void* gmem) {
    uint32_t s = (uint32_t)__cvta_generic_to_shared(smem);
    asm volatile("cp.async.cg.shared.global [%0], [%1], 16;" :: "r"(s), "l"(gmem));
}
#define CP_COMMIT() asm volatile("cp.async.commit_group;")
#define CP_WAIT0()  asm volatile("cp.async.wait_group 0;")

__device__ __forceinline__ void mma16816(float* c, const uint32_t* a, uint32_t b0, uint32_t b1) {
    asm volatile(
        "mma.sync.aligned.m16n8k16.row.col.f32.f16.f16.f32 "
        "{%0,%1,%2,%3},{%4,%5,%6,%7},{%8,%9},{%0,%1,%2,%3};"
        : "+f"(c[0]), "+f"(c[1]), "+f"(c[2]), "+f"(c[3])
        : "r"(a[0]), "r"(a[1]), "r"(a[2]), "r"(a[3]), "r"(b0), "r"(b1));
}
__device__ __forceinline__ uint32_t pack_h2(float x, float y) {
    __half2 h = __floats2half2_rn(x, y);
    return *(uint32_t*)&h;
}
__device__ __forceinline__ float gelu_erf(float x) {
    return 0.5f * x * (1.0f + erff(x * 0.70710678118654752f));
}

// ---------------- weight pre-rounding to fp16 ----------------
__global__ void round_weights(const float* __restrict__ qkvw, const float* __restrict__ projw,
                              const float* __restrict__ fc1w, const float* __restrict__ fc2w,
                              __half* __restrict__ dst)
{
    int stride = gridDim.x * blockDim.x;
    int i0 = blockIdx.x * blockDim.x + threadIdx.x;
    for (int i = i0; i < QKVN*DIMC;   i += stride) dst[OFF_QKVW + i]  = __float2half(qkvw[i]);
    for (int i = i0; i < DIMC*DIMC;   i += stride) dst[OFF_PROJW + i] = __float2half(projw[i]);
    for (int i = i0; i < HIDDEN*DIMC; i += stride) dst[OFF_FC1W + i]  = __float2half(fc1w[i]);
    for (int i = i0; i < DIMC*HIDDEN; i += stride) dst[OFF_FC2W + i]  = __float2half(fc2w[i]);
}

// ---------------- LayerNorm: 1 warp per token ----------------
__global__ void __launch_bounds__(256) ln_fast(
    const float* __restrict__ px, const float* __restrict__ py,
    const float* __restrict__ w,  const float* __restrict__ bsh,
    __half* __restrict__ out)
{
    int wi = threadIdx.x >> 5, lane = threadIdx.x & 31;
    int t  = blockIdx.x*8 + wi;
    int bb = t / MTOK, pos = t - bb*MTOK;
    const float* src = (pos < NX)
        ? px + (size_t)(bb*NX + pos)*DIMC
        : py + (size_t)(bb*NY + pos - NX)*DIMC;

    float4 v[3];
    float s = 0.f, sq = 0.f;
    #pragma unroll
    for (int i = 0; i < 3; i++) {
        v[i] = ((const float4*)src)[lane + 32*i];
        s  += v[i].x + v[i].y + v[i].z + v[i].w;
        sq += v[i].x*v[i].x + v[i].y*v[i].y + v[i].z*v[i].z + v[i].w*v[i].w;
    }
    #pragma unroll
    for (int o = 16; o; o >>= 1) {
        s  += __shfl_xor_sync(0xffffffffu, s,  o);
        sq += __shfl_xor_sync(0xffffffffu, sq, o);
    }
    float mean = s * (1.0f/DIMC);
    float inv  = rsqrtf(sq * (1.0f/DIMC) - mean*mean + LN_EPS);

    uint32_t* op = (uint32_t*)(out + (size_t)t*DIMC);
    #pragma unroll
    for (int i = 0; i < 3; i++) {
        int idx4 = lane + 32*i;
        float4 ww = ((const float4*)w)[idx4];
        float4 bb4 = ((const float4*)bsh)[idx4];
        op[2*idx4]   = pack_h2((v[i].x-mean)*inv*ww.x + bb4.x, (v[i].y-mean)*inv*ww.y + bb4.y);
        op[2*idx4+1] = pack_h2((v[i].z-mean)*inv*ww.z + bb4.z, (v[i].w-mean)*inv*ww.w + bb4.w);
    }
}

// ---------------- pairwise epilogue for fp32-residual outputs ----------------
template<int EPI>
__device__ __forceinline__ void epi_res2(int m, int n, float v0, float v1,
    const float* __restrict__ bias,
    const float* __restrict__ resx, const float* __restrict__ resy,
    float* __restrict__ outx, float* __restrict__ outy)
{
    float2 bv = *(const float2*)(bias + n);
    int bb  = m / MTOK;
    int pos = m - bb * MTOK;
    size_t idx;
    float* outp;
    const float* resp;
    if (pos < NX) {
        idx = ((size_t)(bb*NX + pos))*DIMC + n;
        outp = outx;
        resp = (EPI == 1) ? resx : outx;
    } else {
        idx = ((size_t)(bb*NY + pos - NX))*DIMC + n;
        outp = outy;
        resp = (EPI == 1) ? resy : outy;
    }
    float2 r = *(const float2*)(resp + idx);
    float2 o = make_float2(v0 + bv.x + r.x, v1 + bv.y + r.y);
    *(float2*)(outp + idx) = o;
}

// ---------------- raw-PTX fp16 GEMM (R13-proven): register-direct epilogue ----------------
template<int EPI>
__global__ void __launch_bounds__(256, 2) gemm_raw(
    const __half* __restrict__ A, const __half* __restrict__ W,
    const float* __restrict__ bias, __half* __restrict__ C,
    int M, int N, int K,
    const float* __restrict__ resx, const float* __restrict__ resy,
    float* __restrict__ outx, float* __restrict__ outy)
{
    extern __shared__ __align__(16) char dsm[];
    __half* Ab[2] = { (__half*)(dsm),              (__half*)(dsm + GT_BYTES)   };
    __half* Wb[2] = { (__half*)(dsm + 2*GT_BYTES), (__half*)(dsm + 3*GT_BYTES) };

    int tid = threadIdx.x;
    int w = tid >> 5, lane = tid & 31;
    int g = lane >> 2, t = lane & 3;
    int wm = w >> 1, wn = w & 1;
    int m0 = blockIdx.y << 7;
    int n0 = blockIdx.x << 7;

    float acc[2][8][4];
    #pragma unroll
    for (int i = 0; i < 2; i++)
        #pragma unroll
        for (int j = 0; j < 8; j++)
            #pragma unroll
            for (int c = 0; c < 4; c++) acc[i][j][c] = 0.f;

    int T = K >> 6;
    {
        #pragma unroll
        for (int i = 0; i < 4; i++) {
            int idx = tid + i*256;
            int row = idx >> 3, c8 = (idx & 7) << 3;
            cp16(Ab[0] + row*HTS + c8, A + (size_t)(m0+row)*K + c8);
            cp16(Wb[0] + row*HTS + c8, W + (size_t)(n0+row)*K + c8);
        }
        CP_COMMIT();
    }

    for (int tt = 0; tt < T; tt++) {
        CP_WAIT0();
        __syncthreads();
        if (tt + 1 < T) {
            int k0 = (tt+1) << 6;
            __half* An = Ab[(tt+1)&1];
            __half* Wn = Wb[(tt+1)&1];
            #pragma unroll
            for (int i = 0; i < 4; i++) {
                int idx = tid + i*256;
                int row = idx >> 3, c8 = (idx & 7) << 3;
                cp16(An + row*HTS + c8, A + (size_t)(m0+row)*K + k0 + c8);
                cp16(Wn + row*HTS + c8, W + (size_t)(n0+row)*K + k0 + c8);
            }
            CP_COMMIT();
        }
        const uint32_t* Au = (const uint32_t*)Ab[tt&1];
        const uint32_t* Wu = (const uint32_t*)Wb[tt&1];

        #pragma unroll
        for (int ks = 0; ks < 4; ks++) {
            int ko = ks << 3;
            uint32_t a0[4], a1[4];
            {
                int ar = (wm*32 + g)*36 + ko + t;
                a0[0] = Au[ar];          a0[1] = Au[ar + 8*36];
                a0[2] = Au[ar + 4];      a0[3] = Au[ar + 8*36 + 4];
                int ar1 = ar + 16*36;
                a1[0] = Au[ar1];         a1[1] = Au[ar1 + 8*36];
                a1[2] = Au[ar1 + 4];     a1[3] = Au[ar1 + 8*36 + 4];
            }
            #pragma unroll
            for (int j = 0; j < 8; j++) {
                int br = (wn*64 + 8*j + g)*36 + ko + t;
                uint32_t b0 = Wu[br], b1 = Wu[br + 4];
                mma16816(acc[0][j], a0, b0, b1);
                mma16816(acc[1][j], a1, b0, b1);
            }
        }
        __syncthreads();
    }

    #pragma unroll
    for (int i = 0; i < 2; i++) {
        int row0 = m0 + wm*32 + i*16 + g;
        int row1 = row0 + 8;
        #pragma unroll
        for (int j = 0; j < 8; j++) {
            int col = n0 + wn*64 + j*8 + 2*t;
            float c0 = acc[i][j][0], c1 = acc[i][j][1];
            float c2 = acc[i][j][2], c3 = acc[i][j][3];
            if (EPI == 0) {
                *(uint32_t*)(C + (size_t)row0*N + col) = pack_h2(c0, c1);
                *(uint32_t*)(C + (size_t)row1*N + col) = pack_h2(c2, c3);
            } else if (EPI == 2) {
                float2 bv = *(const float2*)(bias + col);
                *(uint32_t*)(C + (size_t)row0*N + col) =
                    pack_h2(gelu_erf(c0 + bv.x), gelu_erf(c1 + bv.y));
                *(uint32_t*)(C + (size_t)row1*N + col) =
                    pack_h2(gelu_erf(c2 + bv.x), gelu_erf(c3 + bv.y));
            } else {
                epi_res2<EPI>(row0, col, c0, c1, bias, resx, resy, outx, outy);
                epi_res2<EPI>(row1, col, c2, c3, bias, resx, resy, outx, outy);
            }
        }
    }
}

// ---------------- unified attention: self(x2 split) + cross(x4 split) in one grid ----------------
// blockIdx.x: [0,32) self items (qb = idx>>1, sp = idx&1, klen 1024),
//             [32,40) cross items (qb = (idx-32)>>2, sp = (idx-32)&3, klen 576).
// All CTAs write unnormalized partials (pO, pL); merge_all normalizes.
__global__ void __launch_bounds__(256, 2) attn_uni(
    const __half* __restrict__ qkvh,
    float* __restrict__ pO, float* __restrict__ pL)
{
    extern __shared__ __align__(16) char dsm[];
    __half* Kb[2] = { (__half*)(dsm),               (__half*)(dsm + 64*HTS*2)   };
    __half* Vb[2] = { (__half*)(dsm + 2*64*HTS*2),  (__half*)(dsm + 3*64*HTS*2) };

    int tid = threadIdx.x, w = tid >> 5, lane = tid & 31;
    int g = lane >> 2, t = lane & 3;
    int h = blockIdx.y, b = blockIdx.z;

    int idx = blockIdx.x;
    int qblk, slot, q0, koff, klen;
    if (idx < SQB*SSPLIT) {
        qblk = idx >> 1;  slot = idx & 1;
        q0 = qblk << 7;
        klen = NX / SSPLIT;              // 1024
        koff = slot * klen;
    } else {
        int c = idx - SQB*SSPLIT;
        int qb = c >> 2;  slot = c & 3;
        qblk = SQB + qb;
        q0 = NX + (qb << 7);
        klen = MTOK / CSPLIT;            // 576
        koff = slot * klen;
    }

    uint32_t qa[4][4];
    {
        const __half* qrow0 = qkvh + (size_t)(b*MTOK + q0 + w*16 + g)*QKVN + h*HD;
        const __half* qrow1 = qrow0 + 8*QKVN;
        #pragma unroll
        for (int c = 0; c < 4; c++) {
            qa[c][0] = *(const uint32_t*)(qrow0 + 16*c     + 2*t);
            qa[c][1] = *(const uint32_t*)(qrow1 + 16*c     + 2*t);
            qa[c][2] = *(const uint32_t*)(qrow0 + 16*c + 8 + 2*t);
            qa[c][3] = *(const uint32_t*)(qrow1 + 16*c + 8 + 2*t);
        }
    }

    float oac[8][4];
    #pragma unroll
    for (int j = 0; j < 8; j++)
        #pragma unroll
        for (int c = 0; c < 4; c++) oac[j][c] = 0.f;
    float rs0 = 0.f, rs1 = 0.f;

    const __half* kbase = qkvh + ((size_t)b*MTOK)*QKVN + DIMC   + h*HD;
    const __half* vbase = qkvh + ((size_t)b*MTOK)*QKVN + 2*DIMC + h*HD;

    int T = klen >> 6;
    {
        #pragma unroll
        for (int i = 0; i < 2; i++) {
            int idx2 = tid + i*256;
            int row = idx2 >> 3, c8 = (idx2 & 7) << 3;
            cp16(Kb[0] + row*HTS + c8, kbase + (size_t)(koff+row)*QKVN + c8);
            cp16(Vb[0] + row*HTS + c8, vbase + (size_t)(koff+row)*QKVN + c8);
        }
        CP_COMMIT();
    }

    for (int it = 0; it < T; it++) {
        CP_WAIT0();
        __syncthreads();
        if (it + 1 < T) {
            int kt = koff + ((it+1) << 6);
            __half* Kn = Kb[(it+1)&1];
            __half* Vn = Vb[(it+1)&1];
            #pragma unroll
            for (int i = 0; i < 2; i++) {
                int idx2 = tid + i*256;
                int row = idx2 >> 3, c8 = (idx2 & 7) << 3;
                cp16(Kn + row*HTS + c8, kbase + (size_t)(kt+row)*QKVN + c8);
                cp16(Vn + row*HTS + c8, vbase + (size_t)(kt+row)*QKVN + c8);
            }
            CP_COMMIT();
        }
        const uint32_t* Ku = (const uint32_t*)Kb[it&1];
        __half* Vs = Vb[it&1];

        uint32_t ph[8][2];
        #pragma unroll
        for (int j = 0; j < 8; j++) {
            float sc[4] = {0.f, 0.f, 0.f, 0.f};
            int krow = (8*j + g)*36 + t;
            #pragma unroll
            for (int c = 0; c < 4; c++)
                mma16816(sc, qa[c], Ku[krow + 8*c], Ku[krow + 8*c + 4]);
            float e0 = __expf(sc[0]*ATT_SCALE);
            float e1 = __expf(sc[1]*ATT_SCALE);
            float e2 = __expf(sc[2]*ATT_SCALE);
            float e3 = __expf(sc[3]*ATT_SCALE);
            rs0 += e0 + e1;
            rs1 += e2 + e3;
            ph[j][0] = pack_h2(e0, e1);
            ph[j][1] = pack_h2(e2, e3);
        }

        #pragma unroll
        for (int kc = 0; kc < 4; kc++) {
            uint32_t af[4] = { ph[2*kc][0], ph[2*kc][1], ph[2*kc+1][0], ph[2*kc+1][1] };
            #pragma unroll
            for (int jd = 0; jd < 8; jd += 2) {
                int row = 16*kc + ((lane >> 3) & 1)*8 + (lane & 7);
                int col = 8*jd + ((lane >> 4) << 3);
                uint32_t addr = (uint32_t)__cvta_generic_to_shared(Vs + row*HTS + col);
                uint32_t v0, v1, v2, v3;
                asm volatile(
                    "ldmatrix.sync.aligned.m8n8.x4.trans.shared.b16 {%0,%1,%2,%3}, [%4];"
                    : "=r"(v0), "=r"(v1), "=r"(v2), "=r"(v3) : "r"(addr));
                mma16816(oac[jd],   af, v0, v1);
                mma16816(oac[jd+1], af, v2, v3);
            }
        }
    }

    rs0 += __shfl_xor_sync(0xffffffffu, rs0, 1);
    rs0 += __shfl_xor_sync(0xffffffffu, rs0, 2);
    rs1 += __shfl_xor_sync(0xffffffffu, rs1, 1);
    rs1 += __shfl_xor_sync(0xffffffffu, rs1, 2);

    int pidx = ((b*HEADS + h)*QBLKS + qblk)*4 + slot;
    float* dst0 = pO + (size_t)pidx*(128*64) + (w*16 + g)*64;
    float* dst1 = dst0 + 8*64;
    #pragma unroll
    for (int jd = 0; jd < 8; jd++) {
        int col = 8*jd + 2*t;
        *(float2*)(dst0 + col) = make_float2(oac[jd][0], oac[jd][1]);
        *(float2*)(dst1 + col) = make_float2(oac[jd][2], oac[jd][3]);
    }
    if (t == 0) {
        pL[pidx*128 + w*16 + g]     = rs0;
        pL[pidx*128 + w*16 + g + 8] = rs1;
    }
}

// ---------------- merge all attention partials ----------------
__global__ void __launch_bounds__(128) merge_all(
    const float* __restrict__ pO, const float* __restrict__ pL,
    __half* __restrict__ attno)
{
    int qblk = blockIdx.x, h = blockIdx.y, b = blockIdx.z;
    int r = threadIdx.x;
    int ns = (qblk < SQB) ? SSPLIT : CSPLIT;
    int base = ((b*HEADS + h)*QBLKS + qblk)*4;

    float L = 0.f;
    for (int s = 0; s < ns; s++) L += pL[(base+s)*128 + r];
    float inv = 1.f / L;

    int qi = (qblk < SQB) ? (qblk << 7) + r : NX + ((qblk - SQB) << 7) + r;
    __half* op = attno + ((size_t)(b*MTOK + qi))*DIMC + h*HD;
    #pragma unroll
    for (int c4 = 0; c4 < 16; c4++) {
        float4 o = make_float4(0.f, 0.f, 0.f, 0.f);
        for (int s = 0; s < ns; s++) {
            float4 p = *(const float4*)(pO + (size_t)(base+s)*(128*64) + r*64 + c4*4);
            o.x += p.x; o.y += p.y; o.z += p.z; o.w += p.w;
        }
        *(uint32_t*)(op + c4*4)     = pack_h2(o.x*inv, o.y*inv);
        *(uint32_t*)(op + c4*4 + 2) = pack_h2(o.z*inv, o.w*inv);
    }
}

// ---------------- launch ----------------
extern "C" void kernel_launch(void* const* d_in, const int* in_sizes, int n_in,
                              void* d_out, int out_size)
{
    const float* x     = (const float*)d_in[0];
    const float* y     = (const float*)d_in[1];
    const float* n1w   = (const float*)d_in[2];
    const float* n1b   = (const float*)d_in[3];
    const float* n2w   = (const float*)d_in[4];
    const float* n2b   = (const float*)d_in[5];
    const float* qkvw  = (const float*)d_in[6];
    const float* projw = (const float*)d_in[7];
    const float* projb = (const float*)d_in[8];
    const float* fc1w  = (const float*)d_in[9];
    const float* fc1bb = (const float*)d_in[10];
    const float* fc2w  = (const float*)d_in[11];
    const float* fc2b  = (const float*)d_in[12];
    (void)in_sizes; (void)n_in; (void)out_size;

    float* outx = (float*)d_out;
    float* outy = outx + (size_t)BATCH*NX*DIMC;

    __half *catln, *qkvh, *attno, *ln2o, *fc1o, *wrnd;
    float *pO, *pL;
    cudaGetSymbolAddress((void**)&catln, g_catln);
    cudaGetSymbolAddress((void**)&qkvh,  g_qkvh);
    cudaGetSymbolAddress((void**)&attno, g_attno);
    cudaGetSymbolAddress((void**)&ln2o,  g_ln2);
    cudaGetSymbolAddress((void**)&fc1o,  g_fc1);
    cudaGetSymbolAddress((void**)&wrnd,  g_wrnd);
    cudaGetSymbolAddress((void**)&pO,    g_pO);
    cudaGetSymbolAddress((void**)&pL,    g_pL);

    cudaFuncSetAttribute(gemm_raw<0>, cudaFuncAttributeMaxDynamicSharedMemorySize, SMEM_GEMM);
    cudaFuncSetAttribute(gemm_raw<1>, cudaFuncAttributeMaxDynamicSharedMemorySize, SMEM_GEMM);
    cudaFuncSetAttribute(gemm_raw<2>, cudaFuncAttributeMaxDynamicSharedMemorySize, SMEM_GEMM);
    cudaFuncSetAttribute(gemm_raw<3>, cudaFuncAttributeMaxDynamicSharedMemorySize, SMEM_GEMM);
    cudaFuncSetAttribute(attn_uni,    cudaFuncAttributeMaxDynamicSharedMemorySize, SMEM_ATTN5);

    // 0) pre-round weights to fp16
    round_weights<<<256, 256>>>(qkvw, projw, fc1w, fc2w, wrnd);
    // 1) LN1 over concat(x, y)
    ln_fast<<<TTOK/8, 256>>>(x, y, n1w, n1b, catln);
    // 2) fused QKV GEMM
    gemm_raw<0><<<dim3(QKVN/128, TTOK/128), 256, SMEM_GEMM>>>(catln, wrnd + OFF_QKVW, nullptr, qkvh,
        TTOK, QKVN, DIMC, nullptr, nullptr, nullptr, nullptr);
    // 3) ALL attention (self split x2 + cross split x4) in one launch
    attn_uni<<<dim3(ITEMS, HEADS, BATCH), 256, SMEM_ATTN5>>>(qkvh, pO, pL);
    // 4) merge all partials
    merge_all<<<dim3(QBLKS, HEADS, BATCH), 128>>>(pO, pL, attno);
    // 5) output projection + bias + input residual -> d_out
    gemm_raw<1><<<dim3(DIMC/128, TTOK/128), 256, SMEM_GEMM>>>(attno, wrnd + OFF_PROJW, projb, nullptr,
        TTOK, DIMC, DIMC, x, y, outx, outy);
    // 6) LN2 over d_out
    ln_fast<<<TTOK/8, 256>>>(outx, outy, n2w, n2b, ln2o);
    // 7) fc1 + bias + exact GELU
    gemm_raw<2><<<dim3(HIDDEN/128, TTOK/128), 256, SMEM_GEMM>>>(ln2o, wrnd + OFF_FC1W, fc1bb, fc1o,
        TTOK, HIDDEN, DIMC, nullptr, nullptr, nullptr, nullptr);
    // 8) fc2 + bias + residual (in place on d_out)
    gemm_raw<3><<<dim3(DIMC/128, TTOK/128), 256, SMEM_GEMM>>>(fc1o, wrnd + OFF_FC2W, fc2b, nullptr,
        TTOK, DIMC, HIDDEN, nullptr, nullptr, outx, outy);
}

// round 15
// speedup vs baseline: 1.6499x; 1.6499x over previous
#include <cuda_runtime.h>
#include <cuda_fp16.h>
#include <math.h>
#include <stdint.h>

// ---------------- problem constants ----------------
#define DIMC   384
#define HEADS  6
#define HD     64
#define HIDDEN 1536
#define BATCH  4
#define NX     2048
#define NY     256
#define MTOK   2304
#define TTOK   (BATCH*MTOK)          // 9216
#define QKVN   (3*DIMC)              // 1152
#define ATT_SCALE 0.125f
#define LN_EPS 1e-5f

#define HTS 72                       // half row stride (elements); 144B = 36 u32

// attention smem: K/V double buffers only
#define SMEM_ATTN5 (4*64*HTS*2)      // 36,864 B
#define KV_BYTES   (64*HTS*2)        // one K or V tile buffer

// GEMM smem: A/W tiles 128x64 halves, double buffered
#define GT_BYTES (128*HTS*2)         // 18,432 per tile buffer
#define SMEM_GEMM (4*GT_BYTES)       // 73,728 B

#define NSPLIT 4
#define KSPLIT (MTOK/NSPLIT)         // 576
#define QBY    (NY/128)              // 2

// weight scratch offsets (half weights)
#define OFF_QKVW 0
#define OFF_PROJW (QKVN*DIMC)
#define OFF_FC1W  (OFF_PROJW + DIMC*DIMC)
#define OFF_FC2W  (OFF_FC1W + HIDDEN*DIMC)
#define W_TOTAL   (OFF_FC2W + DIMC*HIDDEN)

// ---------------- scratch ----------------
__device__ __half g_catln[TTOK*DIMC];
__device__ __half g_qkvh [TTOK*QKVN];
__device__ __half g_attno[TTOK*DIMC];
__device__ __half g_ln2  [TTOK*DIMC];
__device__ __half g_fc1  [TTOK*HIDDEN];
__device__ __half g_wrnd [W_TOTAL];
__device__ float  g_pO   [BATCH*HEADS*QBY*NSPLIT*128*64];
__device__ float  g_pL   [BATCH*HEADS*QBY*NSPLIT*128];

// ---------------- helpers ----------------
__device__ __forceinline__ void cp16(void* smem, const void* gmem) {
    uint32_t s = (uint32_t)__cvta_generic_to_shared(smem);
    asm volatile("cp.async.cg.shared.global [%0], [%1], 16;" :: "r"(s), "l"(gmem));
}
#define CP_COMMIT() asm volatile("cp.async.commit_group;")
#define CP_WAIT0()  asm volatile("cp.async.wait_group 0;")

__device__ __forceinline__ void mma16816(float* c, const uint32_t* a, uint32_t b0, uint32_t b1) {
    asm volatile(
        "mma.sync.aligned.m16n8k16.row.col.f32.f16.f16.f32 "
        "{%0,%1,%2,%3},{%4,%5,%6,%7},{%8,%9},{%0,%1,%2,%3};"
        : "+f"(c[0]), "+f"(c[1]), "+f"(c[2]), "+f"(c[3])
        : "r"(a[0]), "r"(a[1]), "r"(a[2]), "r"(a[3]), "r"(b0), "r"(b1));
}
__device__ __forceinline__ void ldsm4(uint32_t& d0, uint32_t& d1, uint32_t& d2, uint32_t& d3,
                                      uint32_t addr) {
    asm volatile("ldmatrix.sync.aligned.m8n8.x4.shared.b16 {%0,%1,%2,%3}, [%4];"
        : "=r"(d0), "=r"(d1), "=r"(d2), "=r"(d3) : "r"(addr));
}
__device__ __forceinline__ uint32_t pack_h2(float x, float y) {
    __half2 h = __floats2half2_rn(x, y);
    return *(uint32_t*)&h;
}
__device__ __forceinline__ float gelu_erf(float x) {
    return 0.5f * x * (1.0f + erff(x * 0.70710678118654752f));
}

// ---------------- weight pre-rounding to fp16 ----------------
__global__ void round_weights(const float* __restrict__ qkvw, const float* __restrict__ projw,
                              const float* __restrict__ fc1w, const float* __restrict__ fc2w,
                              __half* __restrict__ dst)
{
    int stride = gridDim.x * blockDim.x;
    int i0 = blockIdx.x * blockDim.x + threadIdx.x;
    for (int i = i0; i < QKVN*DIMC;   i += stride) dst[OFF_QKVW + i]  = __float2half(qkvw[i]);
    for (int i = i0; i < DIMC*DIMC;   i += stride) dst[OFF_PROJW + i] = __float2half(projw[i]);
    for (int i = i0; i < HIDDEN*DIMC; i += stride) dst[OFF_FC1W + i]  = __float2half(fc1w[i]);
    for (int i = i0; i < DIMC*HIDDEN; i += stride) dst[OFF_FC2W + i]  = __float2half(fc2w[i]);
}

// ---------------- LayerNorm: 1 warp per token ----------------
__global__ void __launch_bounds__(256) ln_fast(
    const float* __restrict__ px, const float* __restrict__ py,
    const float* __restrict__ w,  const float* __restrict__ bsh,
    __half* __restrict__ out)
{
    int wi = threadIdx.x >> 5, lane = threadIdx.x & 31;
    int t  = blockIdx.x*8 + wi;
    int bb = t / MTOK, pos = t - bb*MTOK;
    const float* src = (pos < NX)
        ? px + (size_t)(bb*NX + pos)*DIMC
        : py + (size_t)(bb*NY + pos - NX)*DIMC;

    float4 v[3];
    float s = 0.f, sq = 0.f;
    #pragma unroll
    for (int i = 0; i < 3; i++) {
        v[i] = ((const float4*)src)[lane + 32*i];
        s  += v[i].x + v[i].y + v[i].z + v[i].w;
        sq += v[i].x*v[i].x + v[i].y*v[i].y + v[i].z*v[i].z + v[i].w*v[i].w;
    }
    #pragma unroll
    for (int o = 16; o; o >>= 1) {
        s  += __shfl_xor_sync(0xffffffffu, s,  o);
        sq += __shfl_xor_sync(0xffffffffu, sq, o);
    }
    float mean = s * (1.0f/DIMC);
    float inv  = rsqrtf(sq * (1.0f/DIMC) - mean*mean + LN_EPS);

    uint32_t* op = (uint32_t*)(out + (size_t)t*DIMC);
    #pragma unroll
    for (int i = 0; i < 3; i++) {
        int idx4 = lane + 32*i;
        float4 ww = ((const float4*)w)[idx4];
        float4 bb4 = ((const float4*)bsh)[idx4];
        op[2*idx4]   = pack_h2((v[i].x-mean)*inv*ww.x + bb4.x, (v[i].y-mean)*inv*ww.y + bb4.y);
        op[2*idx4+1] = pack_h2((v[i].z-mean)*inv*ww.z + bb4.z, (v[i].w-mean)*inv*ww.w + bb4.w);
    }
}

// ---------------- pairwise epilogue for fp32-residual outputs ----------------
template<int EPI>
__device__ __forceinline__ void epi_res2(int m, int n, float v0, float v1,
    const float* __restrict__ bias,
    const float* __restrict__ resx, const float* __restrict__ resy,
    float* __restrict__ outx, float* __restrict__ outy)
{
    float2 bv = *(const float2*)(bias + n);
    int bb  = m / MTOK;
    int pos = m - bb * MTOK;
    size_t idx;
    float* outp;
    const float* resp;
    if (pos < NX) {
        idx = ((size_t)(bb*NX + pos))*DIMC + n;
        outp = outx;
        resp = (EPI == 1) ? resx : outx;
    } else {
        idx = ((size_t)(bb*NY + pos - NX))*DIMC + n;
        outp = outy;
        resp = (EPI == 1) ? resy : outy;
    }
    float2 r = *(const float2*)(resp + idx);
    float2 o = make_float2(v0 + bv.x + r.x, v1 + bv.y + r.y);
    *(float2*)(outp + idx) = o;
}

// ---------------- raw-PTX fp16 GEMM: ldmatrix fragments, register-direct epilogue ----------------
// C[M,N] = A[M,K] * W[N,K]^T. Block 128x128, 8 warps (4x2), warp 32x64,
// k-tile 64 cp.async double-buffered. acc[2][8][4] in registers.
template<int EPI>
__global__ void __launch_bounds__(256, 2) gemm_raw(
    const __half* __restrict__ A, const __half* __restrict__ W,
    const float* __restrict__ bias, __half* __restrict__ C,
    int M, int N, int K,
    const float* __restrict__ resx, const float* __restrict__ resy,
    float* __restrict__ outx, float* __restrict__ outy)
{
    extern __shared__ __align__(16) char dsm[];
    __half* Ab[2] = { (__half*)(dsm),              (__half*)(dsm + GT_BYTES)   };
    __half* Wb[2] = { (__half*)(dsm + 2*GT_BYTES), (__half*)(dsm + 3*GT_BYTES) };

    int tid = threadIdx.x;
    int w = tid >> 5, lane = tid & 31;
    int g = lane >> 2, t = lane & 3;
    int wm = w >> 1, wn = w & 1;
    int m0 = blockIdx.y << 7;
    int n0 = blockIdx.x << 7;

    // ldmatrix lane addressing (A: seg0 r+0/b0, seg1 r+8/b0, seg2 r+0/b16, seg3 r+8/b16;
    //                           B: seg0 r+0/b0, seg1 r+0/b16, seg2 r+8/b0, seg3 r+8/b16)
    int seg = lane >> 3, r7 = lane & 7;
    uint32_t aBase = (uint32_t)__cvta_generic_to_shared(Ab[0]) +
        (uint32_t)((wm*32 + r7 + ((seg & 1) << 3))*144 + ((seg >> 1) << 4));
    uint32_t bBase = (uint32_t)__cvta_generic_to_shared(Wb[0]) +
        (uint32_t)((wn*64 + r7 + ((seg & 2) << 2))*144 + ((seg & 1) << 4));

    float acc[2][8][4];
    #pragma unroll
    for (int i = 0; i < 2; i++)
        #pragma unroll
        for (int j = 0; j < 8; j++)
            #pragma unroll
            for (int c = 0; c < 4; c++) acc[i][j][c] = 0.f;

    int T = K >> 6;
    {
        #pragma unroll
        for (int i = 0; i < 4; i++) {
            int idx = tid + i*256;
            int row = idx >> 3, c8 = (idx & 7) << 3;
            cp16(Ab[0] + row*HTS + c8, A + (size_t)(m0+row)*K + c8);
            cp16(Wb[0] + row*HTS + c8, W + (size_t)(n0+row)*K + c8);
        }
        CP_COMMIT();
    }

    for (int tt = 0; tt < T; tt++) {
        CP_WAIT0();
        __syncthreads();
        if (tt + 1 < T) {
            int k0 = (tt+1) << 6;
            __half* An = Ab[(tt+1)&1];
            __half* Wn = Wb[(tt+1)&1];
            #pragma unroll
            for (int i = 0; i < 4; i++) {
                int idx = tid + i*256;
                int row = idx >> 3, c8 = (idx & 7) << 3;
                cp16(An + row*HTS + c8, A + (size_t)(m0+row)*K + k0 + c8);
                cp16(Wn + row*HTS + c8, W + (size_t)(n0+row)*K + k0 + c8);
            }
            CP_COMMIT();
        }
        uint32_t aB = aBase + (tt&1)*GT_BYTES;
        uint32_t bB = bBase + (tt&1)*GT_BYTES;

        #pragma unroll
        for (int ks = 0; ks < 4; ks++) {
            uint32_t a0[4], a1[4];
            ldsm4(a0[0], a0[1], a0[2], a0[3], aB + 32*ks);
            ldsm4(a1[0], a1[1], a1[2], a1[3], aB + 16*144 + 32*ks);
            #pragma unroll
            for (int bi = 0; bi < 4; bi++) {
                uint32_t p0, p1, q0, q1;   // (b0,b1) of j=2bi, (b0,b1) of j=2bi+1
                ldsm4(p0, p1, q0, q1, bB + (16*bi)*144 + 32*ks);
                mma16816(acc[0][2*bi],   a0, p0, p1);
                mma16816(acc[1][2*bi],   a1, p0, p1);
                mma16816(acc[0][2*bi+1], a0, q0, q1);
                mma16816(acc[1][2*bi+1], a1, q0, q1);
            }
        }
        __syncthreads();
    }

    #pragma unroll
    for (int i = 0; i < 2; i++) {
        int row0 = m0 + wm*32 + i*16 + g;
        int row1 = row0 + 8;
        #pragma unroll
        for (int j = 0; j < 8; j++) {
            int col = n0 + wn*64 + j*8 + 2*t;
            float c0 = acc[i][j][0], c1 = acc[i][j][1];
            float c2 = acc[i][j][2], c3 = acc[i][j][3];
            if (EPI == 0) {
                *(uint32_t*)(C + (size_t)row0*N + col) = pack_h2(c0, c1);
                *(uint32_t*)(C + (size_t)row1*N + col) = pack_h2(c2, c3);
            } else if (EPI == 2) {
                float2 bv = *(const float2*)(bias + col);
                *(uint32_t*)(C + (size_t)row0*N + col) =
                    pack_h2(gelu_erf(c0 + bv.x), gelu_erf(c1 + bv.y));
                *(uint32_t*)(C + (size_t)row1*N + col) =
                    pack_h2(gelu_erf(c2 + bv.x), gelu_erf(c3 + bv.y));
            } else {
                epi_res2<EPI>(row0, col, c0, c1, bias, resx, resy, outx, outy);
                epi_res2<EPI>(row1, col, c2, c3, bias, resx, resy, outx, outy);
            }
        }
    }
}

// ---------------- attention v6: ldmatrix K-fragments, register S/P/O ----------------
template<bool SPLIT>
__global__ void __launch_bounds__(256, 2) attn_v6(
    const __half* __restrict__ qkvh, __half* __restrict__ attno,
    float* __restrict__ pO, float* __restrict__ pL,
    int q_base, int klen)
{
    extern __shared__ __align__(16) char dsm[];
    __half* Kb[2] = { (__half*)(dsm),              (__half*)(dsm + KV_BYTES)   };
    __half* Vb[2] = { (__half*)(dsm + 2*KV_BYTES), (__half*)(dsm + 3*KV_BYTES) };

    int tid = threadIdx.x, w = tid >> 5, lane = tid & 31;
    int g = lane >> 2, t = lane & 3;
    int h = blockIdx.y, b = blockIdx.z;
    int qb, sp;
    if (SPLIT) { qb = blockIdx.x >> 2; sp = blockIdx.x & 3; }
    else       { qb = blockIdx.x;      sp = 0; }
    int q0   = q_base + (qb << 7);
    int koff = SPLIT ? sp * klen : 0;

    // K b-fragment ldmatrix base (B-style lane map)
    int seg = lane >> 3, r7 = lane & 7;
    uint32_t kBase = (uint32_t)__cvta_generic_to_shared(Kb[0]) +
        (uint32_t)((r7 + ((seg & 2) << 2))*144 + ((seg & 1) << 4));

    uint32_t qa[4][4];
    {
        const __half* qrow0 = qkvh + (size_t)(b*MTOK + q0 + w*16 + g)*QKVN + h*HD;
        const __half* qrow1 = qrow0 + 8*QKVN;
        #pragma unroll
        for (int c = 0; c < 4; c++) {
            qa[c][0] = *(const uint32_t*)(qrow0 + 16*c     + 2*t);
            qa[c][1] = *(const uint32_t*)(qrow1 + 16*c     + 2*t);
            qa[c][2] = *(const uint32_t*)(qrow0 + 16*c + 8 + 2*t);
            qa[c][3] = *(const uint32_t*)(qrow1 + 16*c + 8 + 2*t);
        }
    }

    float oac[8][4];
    #pragma unroll
    for (int j = 0; j < 8; j++)
        #pragma unroll
        for (int c = 0; c < 4; c++) oac[j][c] = 0.f;
    float rs0 = 0.f, rs1 = 0.f;

    const __half* kbase = qkvh + ((size_t)b*MTOK)*QKVN + DIMC   + h*HD;
    const __half* vbase = qkvh + ((size_t)b*MTOK)*QKVN + 2*DIMC + h*HD;

    int T = klen >> 6;
    {
        #pragma unroll
        for (int i = 0; i < 2; i++) {
            int idx = tid + i*256;
            int row = idx >> 3, c8 = (idx & 7) << 3;
            cp16(Kb[0] + row*HTS + c8, kbase + (size_t)(koff+row)*QKVN + c8);
            cp16(Vb[0] + row*HTS + c8, vbase + (size_t)(koff+row)*QKVN + c8);
        }
        CP_COMMIT();
    }

    for (int it = 0; it < T; it++) {
        CP_WAIT0();
        __syncthreads();
        if (it + 1 < T) {
            int kt = koff + ((it+1) << 6);
            __half* Kn = Kb[(it+1)&1];
            __half* Vn = Vb[(it+1)&1];
            #pragma unroll
            for (int i = 0; i < 2; i++) {
                int idx = tid + i*256;
                int row = idx >> 3, c8 = (idx & 7) << 3;
                cp16(Kn + row*HTS + c8, kbase + (size_t)(kt+row)*QKVN + c8);
                cp16(Vn + row*HTS + c8, vbase + (size_t)(kt+row)*QKVN + c8);
            }
            CP_COMMIT();
        }
        uint32_t kB = kBase + (it&1)*KV_BYTES;
        __half* Vs = Vb[it&1];

        // S = Q @ K^T per j-pair; exp in-register; pack P fragments
        uint32_t ph[8][2];
        #pragma unroll
        for (int jp = 0; jp < 4; jp++) {
            float s0[4] = {0.f,0.f,0.f,0.f};
            float s1[4] = {0.f,0.f,0.f,0.f};
            #pragma unroll
            for (int c = 0; c < 4; c++) {
                uint32_t p0, p1, q0r, q1r;
                ldsm4(p0, p1, q0r, q1r, kB + (16*jp)*144 + 32*c);
                mma16816(s0, qa[c], p0, p1);
                mma16816(s1, qa[c], q0r, q1r);
            }
            float e0 = __expf(s0[0]*ATT_SCALE), e1 = __expf(s0[1]*ATT_SCALE);
            float e2 = __expf(s0[2]*ATT_SCALE), e3 = __expf(s0[3]*ATT_SCALE);
            float f0 = __expf(s1[0]*ATT_SCALE), f1 = __expf(s1[1]*ATT_SCALE);
            float f2 = __expf(s1[2]*ATT_SCALE), f3 = __expf(s1[3]*ATT_SCALE);
            rs0 += e0 + e1 + f0 + f1;
            rs1 += e2 + e3 + f2 + f3;
            ph[2*jp][0]   = pack_h2(e0, e1);
            ph[2*jp][1]   = pack_h2(e2, e3);
            ph[2*jp+1][0] = pack_h2(f0, f1);
            ph[2*jp+1][1] = pack_h2(f2, f3);
        }

        // O += P @ V : A-frags from ph (layout identity), B via ldmatrix.x4.trans
        #pragma unroll
        for (int kc = 0; kc < 4; kc++) {
            uint32_t af[4] = { ph[2*kc][0], ph[2*kc][1], ph[2*kc+1][0], ph[2*kc+1][1] };
            #pragma unroll
            for (int jd = 0; jd < 8; jd += 2) {
                int row = 16*kc + ((lane >> 3) & 1)*8 + (lane & 7);
                int col = 8*jd + ((lane >> 4) << 3);
                uint32_t addr = (uint32_t)__cvta_generic_to_shared(Vs + row*HTS + col);
                uint32_t v0, v1, v2, v3;
                asm volatile(
                    "ldmatrix.sync.aligned.m8n8.x4.trans.shared.b16 {%0,%1,%2,%3}, [%4];"
                    : "=r"(v0), "=r"(v1), "=r"(v2), "=r"(v3) : "r"(addr));
                mma16816(oac[jd],   af, v0, v1);
                mma16816(oac[jd+1], af, v2, v3);
            }
        }
    }

    rs0 += __shfl_xor_sync(0xffffffffu, rs0, 1);
    rs0 += __shfl_xor_sync(0xffffffffu, rs0, 2);
    rs1 += __shfl_xor_sync(0xffffffffu, rs1, 1);
    rs1 += __shfl_xor_sync(0xffffffffu, rs1, 2);

    if (SPLIT) {
        int pidx = ((b*HEADS + h)*QBY + qb)*NSPLIT + sp;
        float* dst0 = pO + (size_t)pidx*(128*64) + (w*16 + g)*64;
        float* dst1 = dst0 + 8*64;
        #pragma unroll
        for (int jd = 0; jd < 8; jd++) {
            int col = 8*jd + 2*t;
            *(float2*)(dst0 + col) = make_float2(oac[jd][0], oac[jd][1]);
            *(float2*)(dst1 + col) = make_float2(oac[jd][2], oac[jd][3]);
        }
        if (t == 0) {
            pL[pidx*128 + w*16 + g]     = rs0;
            pL[pidx*128 + w*16 + g + 8] = rs1;
        }
    } else {
        float inv0 = 1.f / rs0;
        float inv1 = 1.f / rs1;
        __half* orow0 = attno + (size_t)(b*MTOK + q0 + w*16 + g)*DIMC + h*HD;
        __half* orow1 = orow0 + 8*DIMC;
        #pragma unroll
        for (int jd = 0; jd < 8; jd++) {
            int col = 8*jd + 2*t;
            *(uint32_t*)(orow0 + col) = pack_h2(oac[jd][0]*inv0, oac[jd][1]*inv0);
            *(uint32_t*)(orow1 + col) = pack_h2(oac[jd][2]*inv1, oac[jd][3]*inv1);
        }
    }
}

// ---------------- merge split-K partials (cross only) ----------------
__global__ void __launch_bounds__(128) merge_attn(
    const float* __restrict__ pO, const float* __restrict__ pL,
    __half* __restrict__ attno)
{
    int qb = blockIdx.x, h = blockIdx.y, b = blockIdx.z;
    int r = threadIdx.x;
    int base = ((b*HEADS + h)*QBY + qb)*NSPLIT;

    float L = 0.f;
    #pragma unroll
    for (int s = 0; s < NSPLIT; s++) L += pL[(base+s)*128 + r];
    float inv = 1.f / L;

    int qi = NX + (qb << 7) + r;
    __half* op = attno + ((size_t)(b*MTOK + qi))*DIMC + h*HD;
    #pragma unroll 4
    for (int c = 0; c < 64; c++) {
        float o = 0.f;
        #pragma unroll
        for (int s = 0; s < NSPLIT; s++)
            o += pO[(size_t)(base+s)*(128*64) + r*64 + c];
        op[c] = __float2half(o * inv);
    }
}

// ---------------- launch ----------------
extern "C" void kernel_launch(void* const* d_in, const int* in_sizes, int n_in,
                              void* d_out, int out_size)
{
    const float* x     = (const float*)d_in[0];
    const float* y     = (const float*)d_in[1];
    const float* n1w   = (const float*)d_in[2];
    const float* n1b   = (const float*)d_in[3];
    const float* n2w   = (const float*)d_in[4];
    const float* n2b   = (const float*)d_in[5];
    const float* qkvw  = (const float*)d_in[6];
    const float* projw = (const float*)d_in[7];
    const float* projb = (const float*)d_in[8];
    const float* fc1w  = (const float*)d_in[9];
    const float* fc1bb = (const float*)d_in[10];
    const float* fc2w  = (const float*)d_in[11];
    const float* fc2b  = (const float*)d_in[12];
    (void)in_sizes; (void)n_in; (void)out_size;

    float* outx = (float*)d_out;
    float* outy = outx + (size_t)BATCH*NX*DIMC;

    __half *catln, *qkvh, *attno, *ln2o, *fc1o, *wrnd;
    float *pO, *pL;
    cudaGetSymbolAddress((void**)&catln, g_catln);
    cudaGetSymbolAddress((void**)&qkvh,  g_qkvh);
    cudaGetSymbolAddress((void**)&attno, g_attno);
    cudaGetSymbolAddress((void**)&ln2o,  g_ln2);
    cudaGetSymbolAddress((void**)&fc1o,  g_fc1);
    cudaGetSymbolAddress((void**)&wrnd,  g_wrnd);
    cudaGetSymbolAddress((void**)&pO,    g_pO);
    cudaGetSymbolAddress((void**)&pL,    g_pL);

    cudaFuncSetAttribute(gemm_raw<0>, cudaFuncAttributeMaxDynamicSharedMemorySize, SMEM_GEMM);
    cudaFuncSetAttribute(gemm_raw<1>, cudaFuncAttributeMaxDynamicSharedMemorySize, SMEM_GEMM);
    cudaFuncSetAttribute(gemm_raw<2>, cudaFuncAttributeMaxDynamicSharedMemorySize, SMEM_GEMM);
    cudaFuncSetAttribute(gemm_raw<3>, cudaFuncAttributeMaxDynamicSharedMemorySize, SMEM_GEMM);
    cudaFuncSetAttribute(attn_v6<false>, cudaFuncAttributeMaxDynamicSharedMemorySize, SMEM_ATTN5);
    cudaFuncSetAttribute(attn_v6<true>,  cudaFuncAttributeMaxDynamicSharedMemorySize, SMEM_ATTN5);

    // 0) pre-round weights to fp16
    round_weights<<<256, 256>>>(qkvw, projw, fc1w, fc2w, wrnd);
    // 1) LN1 over concat(x, y)
    ln_fast<<<TTOK/8, 256>>>(x, y, n1w, n1b, catln);
    // 2) fused QKV GEMM
    gemm_raw<0><<<dim3(QKVN/128, TTOK/128), 256, SMEM_GEMM>>>(catln, wrnd + OFF_QKVW, nullptr, qkvh,
        TTOK, QKVN, DIMC, nullptr, nullptr, nullptr, nullptr);
    // 3) x self-attention
    attn_v6<false><<<dim3(NX/128, HEADS, BATCH), 256, SMEM_ATTN5>>>(qkvh, attno, nullptr, nullptr, 0, NX);
    // 4) y cross-attention: split-K x4 + merge
    attn_v6<true><<<dim3(QBY*NSPLIT, HEADS, BATCH), 256, SMEM_ATTN5>>>(qkvh, nullptr, pO, pL, NX, KSPLIT);
    merge_attn<<<dim3(QBY, HEADS, BATCH), 128>>>(pO, pL, attno);
    // 5) output projection + bias + input residual -> d_out
    gemm_raw<1><<<dim3(DIMC/128, TTOK/128), 256, SMEM_GEMM>>>(attno, wrnd + OFF_PROJW, projb, nullptr,
        TTOK, DIMC, DIMC, x, y, outx, outy);
    // 6) LN2 over d_out
    ln_fast<<<TTOK/8, 256>>>(outx, outy, n2w, n2b, ln2o);
    // 7) fc1 + bias + exact GELU
    gemm_raw<2><<<dim3(HIDDEN/128, TTOK/128), 256, SMEM_GEMM>>>(ln2o, wrnd + OFF_FC1W, fc1bb, fc1o,
        TTOK, HIDDEN, DIMC, nullptr, nullptr, nullptr, nullptr);
    // 8) fc2 + bias + residual (in place on d_out)
    gemm_raw<3><<<dim3(DIMC/128, TTOK/128), 256, SMEM_GEMM>>>(fc1o, wrnd + OFF_FC2W, fc2b, nullptr,
        TTOK, DIMC, HIDDEN, nullptr, nullptr, outx, outy);
}

// round 16
// speedup vs baseline: 1.6753x; 1.0154x over previous
#include <cuda_runtime.h>
#include <cuda_fp16.h>
#include <math.h>
#include <stdint.h>

// ---------------- problem constants ----------------
#define DIMC   384
#define HEADS  6
#define HD     64
#define HIDDEN 1536
#define BATCH  4
#define NX     2048
#define NY     256
#define MTOK   2304
#define TTOK   (BATCH*MTOK)          // 9216
#define QKVN   (3*DIMC)              // 1152
#define SC_LOG2E 0.18033688011112042f   // 0.125 * log2(e)
#define LN_EPS 1e-5f

#define HTS 72                       // half row stride (elements); 144B = 36 u32

// attention smem: K/V double buffers only
#define SMEM_ATTN5 (4*64*HTS*2)      // 36,864 B
#define KV_BYTES   (64*HTS*2)

// GEMM smem: A/W tiles 128x64 halves, TRIPLE buffered
#define GT_BYTES (128*HTS*2)         // 18,432 per tile buffer
#define SMEM_GEMM (6*GT_BYTES)       // 110,592 B

#define NSPLIT 4
#define KSPLIT (MTOK/NSPLIT)         // 576
#define QBY    (NY/128)              // 2
#define SQB    (NX/128)              // 16
#define AITEMS (SQB + QBY*NSPLIT)    // 24 attention items per (h,b)

// weight scratch offsets (half weights)
#define OFF_QKVW 0
#define OFF_PROJW (QKVN*DIMC)
#define OFF_FC1W  (OFF_PROJW + DIMC*DIMC)
#define OFF_FC2W  (OFF_FC1W + HIDDEN*DIMC)
#define W_TOTAL   (OFF_FC2W + DIMC*HIDDEN)

// ---------------- scratch ----------------
__device__ __half g_catln[TTOK*DIMC];
__device__ __half g_qkvh [TTOK*QKVN];
__device__ __half g_attno[TTOK*DIMC];
__device__ __half g_ln2  [TTOK*DIMC];
__device__ __half g_fc1  [TTOK*HIDDEN];
__device__ __half g_wrnd [W_TOTAL];
__device__ float  g_pO   [BATCH*HEADS*QBY*NSPLIT*128*64];
__device__ float  g_pL   [BATCH*HEADS*QBY*NSPLIT*128];

// ---------------- helpers ----------------
__device__ __forceinline__ void cp16(void* smem, const void* gmem) {
    uint32_t s = (uint32_t)__cvta_generic_to_shared(smem);
    asm volatile("cp.async.cg.shared.global [%0], [%1], 16;" :: "r"(s), "l"(gmem));
}
#define CP_COMMIT() asm volatile("cp.async.commit_group;")
#define CP_WAIT0()  asm volatile("cp.async.wait_group 0;")
#define CP_WAIT1()  asm volatile("cp.async.wait_group 1;")

__device__ __forceinline__ void mma16816(float* c, const uint32_t* a, uint32_t b0, uint32_t b1) {
    asm volatile(
        "mma.sync.aligned.m16n8k16.row.col.f32.f16.f16.f32 "
        "{%0,%1,%2,%3},{%4,%5,%6,%7},{%8,%9},{%0,%1,%2,%3};"
        : "+f"(c[0]), "+f"(c[1]), "+f"(c[2]), "+f"(c[3])
        : "r"(a[0]), "r"(a[1]), "r"(a[2]), "r"(a[3]), "r"(b0), "r"(b1));
}
__device__ __forceinline__ void ldsm4(uint32_t& d0, uint32_t& d1, uint32_t& d2, uint32_t& d3,
                                      uint32_t addr) {
    asm volatile("ldmatrix.sync.aligned.m8n8.x4.shared.b16 {%0,%1,%2,%3}, [%4];"
        : "=r"(d0), "=r"(d1), "=r"(d2), "=r"(d3) : "r"(addr));
}
__device__ __forceinline__ uint32_t pack_h2(float x, float y) {
    __half2 h = __floats2half2_rn(x, y);
    return *(uint32_t*)&h;
}
__device__ __forceinline__ float gelu_erf(float x) {
    return 0.5f * x * (1.0f + erff(x * 0.70710678118654752f));
}

// ---------------- weight pre-rounding to fp16 ----------------
__global__ void round_weights(const float* __restrict__ qkvw, const float* __restrict__ projw,
                              const float* __restrict__ fc1w, const float* __restrict__ fc2w,
                              __half* __restrict__ dst)
{
    int stride = gridDim.x * blockDim.x;
    int i0 = blockIdx.x * blockDim.x + threadIdx.x;
    for (int i = i0; i < QKVN*DIMC;   i += stride) dst[OFF_QKVW + i]  = __float2half(qkvw[i]);
    for (int i = i0; i < DIMC*DIMC;   i += stride) dst[OFF_PROJW + i] = __float2half(projw[i]);
    for (int i = i0; i < HIDDEN*DIMC; i += stride) dst[OFF_FC1W + i]  = __float2half(fc1w[i]);
    for (int i = i0; i < DIMC*HIDDEN; i += stride) dst[OFF_FC2W + i]  = __float2half(fc2w[i]);
}

// ---------------- LayerNorm: 1 warp per token ----------------
__global__ void __launch_bounds__(256) ln_fast(
    const float* __restrict__ px, const float* __restrict__ py,
    const float* __restrict__ w,  const float* __restrict__ bsh,
    __half* __restrict__ out)
{
    int wi = threadIdx.x >> 5, lane = threadIdx.x & 31;
    int t  = blockIdx.x*8 + wi;
    int bb = t / MTOK, pos = t - bb*MTOK;
    const float* src = (pos < NX)
        ? px + (size_t)(bb*NX + pos)*DIMC
        : py + (size_t)(bb*NY + pos - NX)*DIMC;

    float4 v[3];
    float s = 0.f, sq = 0.f;
    #pragma unroll
    for (int i = 0; i < 3; i++) {
        v[i] = ((const float4*)src)[lane + 32*i];
        s  += v[i].x + v[i].y + v[i].z + v[i].w;
        sq += v[i].x*v[i].x + v[i].y*v[i].y + v[i].z*v[i].z + v[i].w*v[i].w;
    }
    #pragma unroll
    for (int o = 16; o; o >>= 1) {
        s  += __shfl_xor_sync(0xffffffffu, s,  o);
        sq += __shfl_xor_sync(0xffffffffu, sq, o);
    }
    float mean = s * (1.0f/DIMC);
    float inv  = rsqrtf(sq * (1.0f/DIMC) - mean*mean + LN_EPS);

    uint32_t* op = (uint32_t*)(out + (size_t)t*DIMC);
    #pragma unroll
    for (int i = 0; i < 3; i++) {
        int idx4 = lane + 32*i;
        float4 ww = ((const float4*)w)[idx4];
        float4 bb4 = ((const float4*)bsh)[idx4];
        op[2*idx4]   = pack_h2((v[i].x-mean)*inv*ww.x + bb4.x, (v[i].y-mean)*inv*ww.y + bb4.y);
        op[2*idx4+1] = pack_h2((v[i].z-mean)*inv*ww.z + bb4.z, (v[i].w-mean)*inv*ww.w + bb4.w);
    }
}

// ---------------- pairwise epilogue for fp32-residual outputs ----------------
template<int EPI>
__device__ __forceinline__ void epi_res2(int m, int n, float v0, float v1,
    const float* __restrict__ bias,
    const float* __restrict__ resx, const float* __restrict__ resy,
    float* __restrict__ outx, float* __restrict__ outy)
{
    float2 bv = *(const float2*)(bias + n);
    int bb  = m / MTOK;
    int pos = m - bb * MTOK;
    size_t idx;
    float* outp;
    const float* resp;
    if (pos < NX) {
        idx = ((size_t)(bb*NX + pos))*DIMC + n;
        outp = outx;
        resp = (EPI == 1) ? resx : outx;
    } else {
        idx = ((size_t)(bb*NY + pos - NX))*DIMC + n;
        outp = outy;
        resp = (EPI == 1) ? resy : outy;
    }
    float2 r = *(const float2*)(resp + idx);
    float2 o = make_float2(v0 + bv.x + r.x, v1 + bv.y + r.y);
    *(float2*)(outp + idx) = o;
}

// ---------------- raw-PTX fp16 GEMM: 3-stage pipeline, ldmatrix, register epilogue ----------------
template<int EPI>
__global__ void __launch_bounds__(256, 2) gemm_raw(
    const __half* __restrict__ A, const __half* __restrict__ W,
    const float* __restrict__ bias, __half* __restrict__ C,
    int M, int N, int K,
    const float* __restrict__ resx, const float* __restrict__ resy,
    float* __restrict__ outx, float* __restrict__ outy)
{
    extern __shared__ __align__(16) char dsm[];
    __half* Abuf = (__half*)dsm;                    // 3 x GT_BYTES
    __half* Wbuf = (__half*)(dsm + 3*GT_BYTES);     // 3 x GT_BYTES

    int tid = threadIdx.x;
    int w = tid >> 5, lane = tid & 31;
    int g = lane >> 2, t = lane & 3;
    int wm = w >> 1, wn = w & 1;
    int m0 = blockIdx.y << 7;
    int n0 = blockIdx.x << 7;

    int seg = lane >> 3, r7 = lane & 7;
    uint32_t aBase = (uint32_t)__cvta_generic_to_shared(Abuf) +
        (uint32_t)((wm*32 + r7 + ((seg & 1) << 3))*144 + ((seg >> 1) << 4));
    uint32_t bBase = (uint32_t)__cvta_generic_to_shared(Wbuf) +
        (uint32_t)((wn*64 + r7 + ((seg & 2) << 2))*144 + ((seg & 1) << 4));

    int srow = tid >> 3, sc8 = (tid & 7) << 3;      // staging coords (x4 iterations)

    float acc[2][8][4];
    #pragma unroll
    for (int i = 0; i < 2; i++)
        #pragma unroll
        for (int j = 0; j < 8; j++)
            #pragma unroll
            for (int c = 0; c < 4; c++) acc[i][j][c] = 0.f;

    int T = K >> 6;
    // prologue: stage tiles 0 and 1
    #pragma unroll
    for (int p = 0; p < 2; p++) {
        __half* Ad = Abuf + p*(GT_BYTES/2);   // GT_BYTES/2 halves per buffer
        __half* Wd = Wbuf + p*(GT_BYTES/2);
        int k0 = p << 6;
        #pragma unroll
        for (int i = 0; i < 4; i++) {
            int row = srow + i*32;
            cp16(Ad + row*HTS + sc8, A + (size_t)(m0+row)*K + k0 + sc8);
            cp16(Wd + row*HTS + sc8, W + (size_t)(n0+row)*K + k0 + sc8);
        }
        CP_COMMIT();
    }

    for (int tt = 0; tt < T; tt++) {
        if (tt < T-1) { CP_WAIT1(); } else { CP_WAIT0(); }
        __syncthreads();
        if (tt + 2 < T) {
            int bi = (tt+2) % 3;
            __half* Ad = Abuf + bi*(GT_BYTES/2);
            __half* Wd = Wbuf + bi*(GT_BYTES/2);
            int k0 = (tt+2) << 6;
            #pragma unroll
            for (int i = 0; i < 4; i++) {
                int row = srow + i*32;
                cp16(Ad + row*HTS + sc8, A + (size_t)(m0+row)*K + k0 + sc8);
                cp16(Wd + row*HTS + sc8, W + (size_t)(n0+row)*K + k0 + sc8);
            }
            CP_COMMIT();
        }
        int cb = tt % 3;
        uint32_t aB = aBase + cb*GT_BYTES;
        uint32_t bB = bBase + cb*GT_BYTES;

        #pragma unroll
        for (int ks = 0; ks < 4; ks++) {
            uint32_t a0[4], a1[4];
            ldsm4(a0[0], a0[1], a0[2], a0[3], aB + 32*ks);
            ldsm4(a1[0], a1[1], a1[2], a1[3], aB + 16*144 + 32*ks);
            #pragma unroll
            for (int bi = 0; bi < 4; bi++) {
                uint32_t p0, p1, q0, q1;
                ldsm4(p0, p1, q0, q1, bB + (16*bi)*144 + 32*ks);
                mma16816(acc[0][2*bi],   a0, p0, p1);
                mma16816(acc[1][2*bi],   a1, p0, p1);
                mma16816(acc[0][2*bi+1], a0, q0, q1);
                mma16816(acc[1][2*bi+1], a1, q0, q1);
            }
        }
    }

    #pragma unroll
    for (int i = 0; i < 2; i++) {
        int row0 = m0 + wm*32 + i*16 + g;
        int row1 = row0 + 8;
        #pragma unroll
        for (int j = 0; j < 8; j++) {
            int col = n0 + wn*64 + j*8 + 2*t;
            float c0 = acc[i][j][0], c1 = acc[i][j][1];
            float c2 = acc[i][j][2], c3 = acc[i][j][3];
            if (EPI == 0) {
                *(uint32_t*)(C + (size_t)row0*N + col) = pack_h2(c0, c1);
                *(uint32_t*)(C + (size_t)row1*N + col) = pack_h2(c2, c3);
            } else if (EPI == 2) {
                float2 bv = *(const float2*)(bias + col);
                *(uint32_t*)(C + (size_t)row0*N + col) =
                    pack_h2(gelu_erf(c0 + bv.x), gelu_erf(c1 + bv.y));
                *(uint32_t*)(C + (size_t)row1*N + col) =
                    pack_h2(gelu_erf(c2 + bv.x), gelu_erf(c3 + bv.y));
            } else {
                epi_res2<EPI>(row0, col, c0, c1, bias, resx, resy, outx, outy);
                epi_res2<EPI>(row1, col, c2, c3, bias, resx, resy, outx, outy);
            }
        }
    }
}

// ---------------- unified attention: self (direct) + cross (split-K x4) in one grid ----------------
// blockIdx.x in [0,16): self q-block, klen=2048, direct fp16 output.
// blockIdx.x in [16,24): cross item, qb=(i-16)>>2, sp=(i-16)&3, klen=576, split partials.
__global__ void __launch_bounds__(256, 2) attn_v7(
    const __half* __restrict__ qkvh, __half* __restrict__ attno,
    float* __restrict__ pO, float* __restrict__ pL)
{
    extern __shared__ __align__(16) char dsm[];
    __half* Kb[2] = { (__half*)(dsm),              (__half*)(dsm + KV_BYTES)   };
    __half* Vb[2] = { (__half*)(dsm + 2*KV_BYTES), (__half*)(dsm + 3*KV_BYTES) };

    int tid = threadIdx.x, w = tid >> 5, lane = tid & 31;
    int g = lane >> 2, t = lane & 3;
    int h = blockIdx.y, b = blockIdx.z;

    int item = blockIdx.x;
    bool self = (item < SQB);
    int qb, sp, q0, koff, klen;
    if (self) {
        qb = item; sp = 0;
        q0 = qb << 7;
        koff = 0; klen = NX;
    } else {
        int c = item - SQB;
        qb = c >> 2; sp = c & 3;
        q0 = NX + (qb << 7);
        klen = KSPLIT; koff = sp * KSPLIT;
    }

    int seg = lane >> 3, r7 = lane & 7;
    uint32_t kBase = (uint32_t)__cvta_generic_to_shared(Kb[0]) +
        (uint32_t)((r7 + ((seg & 2) << 2))*144 + ((seg & 1) << 4));

    uint32_t qa[4][4];
    {
        const __half* qrow0 = qkvh + (size_t)(b*MTOK + q0 + w*16 + g)*QKVN + h*HD;
        const __half* qrow1 = qrow0 + 8*QKVN;
        #pragma unroll
        for (int c = 0; c < 4; c++) {
            qa[c][0] = *(const uint32_t*)(qrow0 + 16*c     + 2*t);
            qa[c][1] = *(const uint32_t*)(qrow1 + 16*c     + 2*t);
            qa[c][2] = *(const uint32_t*)(qrow0 + 16*c + 8 + 2*t);
            qa[c][3] = *(const uint32_t*)(qrow1 + 16*c + 8 + 2*t);
        }
    }

    float oac[8][4];
    #pragma unroll
    for (int j = 0; j < 8; j++)
        #pragma unroll
        for (int c = 0; c < 4; c++) oac[j][c] = 0.f;
    float rs0 = 0.f, rs1 = 0.f;

    const __half* kbase = qkvh + ((size_t)b*MTOK)*QKVN + DIMC   + h*HD;
    const __half* vbase = qkvh + ((size_t)b*MTOK)*QKVN + 2*DIMC + h*HD;

    int T = klen >> 6;
    {
        #pragma unroll
        for (int i = 0; i < 2; i++) {
            int idx = tid + i*256;
            int row = idx >> 3, c8 = (idx & 7) << 3;
            cp16(Kb[0] + row*HTS + c8, kbase + (size_t)(koff+row)*QKVN + c8);
            cp16(Vb[0] + row*HTS + c8, vbase + (size_t)(koff+row)*QKVN + c8);
        }
        CP_COMMIT();
    }

    for (int it = 0; it < T; it++) {
        CP_WAIT0();
        __syncthreads();
        if (it + 1 < T) {
            int kt = koff + ((it+1) << 6);
            __half* Kn = Kb[(it+1)&1];
            __half* Vn = Vb[(it+1)&1];
            #pragma unroll
            for (int i = 0; i < 2; i++) {
                int idx = tid + i*256;
                int row = idx >> 3, c8 = (idx & 7) << 3;
                cp16(Kn + row*HTS + c8, kbase + (size_t)(kt+row)*QKVN + c8);
                cp16(Vn + row*HTS + c8, vbase + (size_t)(kt+row)*QKVN + c8);
            }
            CP_COMMIT();
        }
        uint32_t kB = kBase + (it&1)*KV_BYTES;
        __half* Vs = Vb[it&1];

        uint32_t ph[8][2];
        #pragma unroll
        for (int jp = 0; jp < 4; jp++) {
            float s0[4] = {0.f,0.f,0.f,0.f};
            float s1[4] = {0.f,0.f,0.f,0.f};
            #pragma unroll
            for (int c = 0; c < 4; c++) {
                uint32_t p0, p1, q0r, q1r;
                ldsm4(p0, p1, q0r, q1r, kB + (16*jp)*144 + 32*c);
                mma16816(s0, qa[c], p0, p1);
                mma16816(s1, qa[c], q0r, q1r);
            }
            float e0 = exp2f(s0[0]*SC_LOG2E), e1 = exp2f(s0[1]*SC_LOG2E);
            float e2 = exp2f(s0[2]*SC_LOG2E), e3 = exp2f(s0[3]*SC_LOG2E);
            float f0 = exp2f(s1[0]*SC_LOG2E), f1 = exp2f(s1[1]*SC_LOG2E);
            float f2 = exp2f(s1[2]*SC_LOG2E), f3 = exp2f(s1[3]*SC_LOG2E);
            rs0 += e0 + e1 + f0 + f1;
            rs1 += e2 + e3 + f2 + f3;
            ph[2*jp][0]   = pack_h2(e0, e1);
            ph[2*jp][1]   = pack_h2(e2, e3);
            ph[2*jp+1][0] = pack_h2(f0, f1);
            ph[2*jp+1][1] = pack_h2(f2, f3);
        }

        #pragma unroll
        for (int kc = 0; kc < 4; kc++) {
            uint32_t af[4] = { ph[2*kc][0], ph[2*kc][1], ph[2*kc+1][0], ph[2*kc+1][1] };
            #pragma unroll
            for (int jd = 0; jd < 8; jd += 2) {
                int row = 16*kc + ((lane >> 3) & 1)*8 + (lane & 7);
                int col = 8*jd + ((lane >> 4) << 3);
                uint32_t addr = (uint32_t)__cvta_generic_to_shared(Vs + row*HTS + col);
                uint32_t v0, v1, v2, v3;
                asm volatile(
                    "ldmatrix.sync.aligned.m8n8.x4.trans.shared.b16 {%0,%1,%2,%3}, [%4];"
                    : "=r"(v0), "=r"(v1), "=r"(v2), "=r"(v3) : "r"(addr));
                mma16816(oac[jd],   af, v0, v1);
                mma16816(oac[jd+1], af, v2, v3);
            }
        }
    }

    rs0 += __shfl_xor_sync(0xffffffffu, rs0, 1);
    rs0 += __shfl_xor_sync(0xffffffffu, rs0, 2);
    rs1 += __shfl_xor_sync(0xffffffffu, rs1, 1);
    rs1 += __shfl_xor_sync(0xffffffffu, rs1, 2);

    if (!self) {
        int pidx = ((b*HEADS + h)*QBY + qb)*NSPLIT + sp;
        float* dst0 = pO + (size_t)pidx*(128*64) + (w*16 + g)*64;
        float* dst1 = dst0 + 8*64;
        #pragma unroll
        for (int jd = 0; jd < 8; jd++) {
            int col = 8*jd + 2*t;
            *(float2*)(dst0 + col) = make_float2(oac[jd][0], oac[jd][1]);
            *(float2*)(dst1 + col) = make_float2(oac[jd][2], oac[jd][3]);
        }
        if (t == 0) {
            pL[pidx*128 + w*16 + g]     = rs0;
            pL[pidx*128 + w*16 + g + 8] = rs1;
        }
    } else {
        float inv0 = 1.f / rs0;
        float inv1 = 1.f / rs1;
        __half* orow0 = attno + (size_t)(b*MTOK + q0 + w*16 + g)*DIMC + h*HD;
        __half* orow1 = orow0 + 8*DIMC;
        #pragma unroll
        for (int jd = 0; jd < 8; jd++) {
            int col = 8*jd + 2*t;
            *(uint32_t*)(orow0 + col) = pack_h2(oac[jd][0]*inv0, oac[jd][1]*inv0);
            *(uint32_t*)(orow1 + col) = pack_h2(oac[jd][2]*inv1, oac[jd][3]*inv1);
        }
    }
}

// ---------------- merge split-K partials (cross only) ----------------
__global__ void __launch_bounds__(128) merge_attn(
    const float* __restrict__ pO, const float* __restrict__ pL,
    __half* __restrict__ attno)
{
    int qb = blockIdx.x, h = blockIdx.y, b = blockIdx.z;
    int r = threadIdx.x;
    int base = ((b*HEADS + h)*QBY + qb)*NSPLIT;

    float L = 0.f;
    #pragma unroll
    for (int s = 0; s < NSPLIT; s++) L += pL[(base+s)*128 + r];
    float inv = 1.f / L;

    int qi = NX + (qb << 7) + r;
    __half* op = attno + ((size_t)(b*MTOK + qi))*DIMC + h*HD;
    #pragma unroll 4
    for (int c = 0; c < 64; c++) {
        float o = 0.f;
        #pragma unroll
        for (int s = 0; s < NSPLIT; s++)
            o += pO[(size_t)(base+s)*(128*64) + r*64 + c];
        op[c] = __float2half(o * inv);
    }
}

// ---------------- launch ----------------
extern "C" void kernel_launch(void* const* d_in, const int* in_sizes, int n_in,
                              void* d_out, int out_size)
{
    const float* x     = (const float*)d_in[0];
    const float* y     = (const float*)d_in[1];
    const float* n1w   = (const float*)d_in[2];
    const float* n1b   = (const float*)d_in[3];
    const float* n2w   = (const float*)d_in[4];
    const float* n2b   = (const float*)d_in[5];
    const float* qkvw  = (const float*)d_in[6];
    const float* projw = (const float*)d_in[7];
    const float* projb = (const float*)d_in[8];
    const float* fc1w  = (const float*)d_in[9];
    const float* fc1bb = (const float*)d_in[10];
    const float* fc2w  = (const float*)d_in[11];
    const float* fc2b  = (const float*)d_in[12];
    (void)in_sizes; (void)n_in; (void)out_size;

    float* outx = (float*)d_out;
    float* outy = outx + (size_t)BATCH*NX*DIMC;

    __half *catln, *qkvh, *attno, *ln2o, *fc1o, *wrnd;
    float *pO, *pL;
    cudaGetSymbolAddress((void**)&catln, g_catln);
    cudaGetSymbolAddress((void**)&qkvh,  g_qkvh);
    cudaGetSymbolAddress((void**)&attno, g_attno);
    cudaGetSymbolAddress((void**)&ln2o,  g_ln2);
    cudaGetSymbolAddress((void**)&fc1o,  g_fc1);
    cudaGetSymbolAddress((void**)&wrnd,  g_wrnd);
    cudaGetSymbolAddress((void**)&pO,    g_pO);
    cudaGetSymbolAddress((void**)&pL,    g_pL);

    cudaFuncSetAttribute(gemm_raw<0>, cudaFuncAttributeMaxDynamicSharedMemorySize, SMEM_GEMM);
    cudaFuncSetAttribute(gemm_raw<1>, cudaFuncAttributeMaxDynamicSharedMemorySize, SMEM_GEMM);
    cudaFuncSetAttribute(gemm_raw<2>, cudaFuncAttributeMaxDynamicSharedMemorySize, SMEM_GEMM);
    cudaFuncSetAttribute(gemm_raw<3>, cudaFuncAttributeMaxDynamicSharedMemorySize, SMEM_GEMM);
    cudaFuncSetAttribute(attn_v7,     cudaFuncAttributeMaxDynamicSharedMemorySize, SMEM_ATTN5);

    // 0) pre-round weights to fp16
    round_weights<<<256, 256>>>(qkvw, projw, fc1w, fc2w, wrnd);
    // 1) LN1 over concat(x, y)
    ln_fast<<<TTOK/8, 256>>>(x, y, n1w, n1b, catln);
    // 2) fused QKV GEMM
    gemm_raw<0><<<dim3(QKVN/128, TTOK/128), 256, SMEM_GEMM>>>(catln, wrnd + OFF_QKVW, nullptr, qkvh,
        TTOK, QKVN, DIMC, nullptr, nullptr, nullptr, nullptr);
    // 3) ALL attention in one launch (self direct + cross split-K)
    attn_v7<<<dim3(AITEMS, HEADS, BATCH), 256, SMEM_ATTN5>>>(qkvh, attno, pO, pL);
    // 4) merge cross partials
    merge_attn<<<dim3(QBY, HEADS, BATCH), 128>>>(pO, pL, attno);
    // 5) output projection + bias + input residual -> d_out
    gemm_raw<1><<<dim3(DIMC/128, TTOK/128), 256, SMEM_GEMM>>>(attno, wrnd + OFF_PROJW, projb, nullptr,
        TTOK, DIMC, DIMC, x, y, outx, outy);
    // 6) LN2 over d_out
    ln_fast<<<TTOK/8, 256>>>(outx, outy, n2w, n2b, ln2o);
    // 7) fc1 + bias + exact GELU
    gemm_raw<2><<<dim3(HIDDEN/128, TTOK/128), 256, SMEM_GEMM>>>(ln2o, wrnd + OFF_FC1W, fc1bb, fc1o,
        TTOK, HIDDEN, DIMC, nullptr, nullptr, nullptr, nullptr);
    // 8) fc2 + bias + residual (in place on d_out)
    gemm_raw<3><<<dim3(DIMC/128, TTOK/128), 256, SMEM_GEMM>>>(fc1o, wrnd + OFF_FC2W, fc2b, nullptr,
        TTOK, DIMC, HIDDEN, nullptr, nullptr, outx, outy);
}

// round 17
// speedup vs baseline: 1.7145x; 1.0234x over previous
#include <cuda_runtime.h>
#include <cuda_fp16.h>
#include <math.h>
#include <stdint.h>

// ---------------- problem constants ----------------
#define DIMC   384
#define HEADS  6
#define HD     64
#define HIDDEN 1536
#define BATCH  4
#define NX     2048
#define NY     256
#define MTOK   2304
#define TTOK   (BATCH*MTOK)          // 9216
#define QKVN   (3*DIMC)              // 1152
#define SC_LOG2E 0.18033688011112042f   // 0.125 * log2(e)
#define LN_EPS 1e-5f

#define HTS 72                       // half row stride (elements); 144B = 36 u32

// attention smem: K/V double buffers only
#define SMEM_ATTN5 (4*64*HTS*2)      // 36,864 B
#define KV_BYTES   (64*HTS*2)

// GEMM smem: A/W tiles 128x64 halves, TRIPLE buffered
#define GT_BYTES (128*HTS*2)         // 18,432 per tile buffer
#define SMEM_GEMM (6*GT_BYTES)       // 110,592 B

#define NSPLIT 4
#define KSPLIT (MTOK/NSPLIT)         // 576
#define QBY    (NY/128)              // 2
#define SQB    (NX/128)              // 16
#define AITEMS (SQB + QBY*NSPLIT)    // 24 attention items per (h,b)

// weight scratch offsets (half weights)
#define OFF_QKVW 0
#define OFF_PROJW (QKVN*DIMC)
#define OFF_FC1W  (OFF_PROJW + DIMC*DIMC)
#define OFF_FC2W  (OFF_FC1W + HIDDEN*DIMC)
#define W_TOTAL   (OFF_FC2W + DIMC*HIDDEN)

// ---------------- scratch ----------------
__device__ __half g_catln[TTOK*DIMC];
__device__ __half g_qkvh [TTOK*QKVN];
__device__ __half g_attno[TTOK*DIMC];
__device__ __half g_ln2  [TTOK*DIMC];
__device__ __half g_fc1  [TTOK*HIDDEN];
__device__ __half g_wrnd [W_TOTAL];
__device__ float  g_pO   [BATCH*HEADS*QBY*NSPLIT*128*64];
__device__ float  g_pL   [BATCH*HEADS*QBY*NSPLIT*128];

// ---------------- helpers ----------------
__device__ __forceinline__ void cp16(void* smem, const void* gmem) {
    uint32_t s = (uint32_t)__cvta_generic_to_shared(smem);
    asm volatile("cp.async.cg.shared.global [%0], [%1], 16;" :: "r"(s), "l"(gmem));
}
#define CP_COMMIT() asm volatile("cp.async.commit_group;")
#define CP_WAIT0()  asm volatile("cp.async.wait_group 0;")
#define CP_WAIT1()  asm volatile("cp.async.wait_group 1;")

__device__ __forceinline__ void mma16816(float* c, const uint32_t* a, uint32_t b0, uint32_t b1) {
    asm volatile(
        "mma.sync.aligned.m16n8k16.row.col.f32.f16.f16.f32 "
        "{%0,%1,%2,%3},{%4,%5,%6,%7},{%8,%9},{%0,%1,%2,%3};"
        : "+f"(c[0]), "+f"(c[1]), "+f"(c[2]), "+f"(c[3])
        : "r"(a[0]), "r"(a[1]), "r"(a[2]), "r"(a[3]), "r"(b0), "r"(b1));
}
__device__ __forceinline__ void ldsm4(uint32_t& d0, uint32_t& d1, uint32_t& d2, uint32_t& d3,
                                      uint32_t addr) {
    asm volatile("ldmatrix.sync.aligned.m8n8.x4.shared.b16 {%0,%1,%2,%3}, [%4];"
        : "=r"(d0), "=r"(d1), "=r"(d2), "=r"(d3) : "r"(addr));
}
__device__ __forceinline__ uint32_t pack_h2(float x, float y) {
    __half2 h = __floats2half2_rn(x, y);
    return *(uint32_t*)&h;
}
__device__ __forceinline__ uint32_t h2exp2(uint32_t x) {
    uint32_t r;
    asm("ex2.approx.f16x2 %0, %1;" : "=r"(r) : "r"(x));
    return r;
}
__device__ __forceinline__ float gelu_erf(float x) {
    return 0.5f * x * (1.0f + erff(x * 0.70710678118654752f));
}

// ---------------- weight pre-rounding to fp16 (vectorized) ----------------
__global__ void round_weights(const float* __restrict__ qkvw, const float* __restrict__ projw,
                              const float* __restrict__ fc1w, const float* __restrict__ fc2w,
                              __half* __restrict__ dst)
{
    int stride = gridDim.x * blockDim.x;
    int i0 = blockIdx.x * blockDim.x + threadIdx.x;
    const float2* q2 = (const float2*)qkvw;   __half2* dq = (__half2*)(dst + OFF_QKVW);
    const float2* p2 = (const float2*)projw;  __half2* dp = (__half2*)(dst + OFF_PROJW);
    const float2* f2 = (const float2*)fc1w;   __half2* df = (__half2*)(dst + OFF_FC1W);
    const float2* g2 = (const float2*)fc2w;   __half2* dg = (__half2*)(dst + OFF_FC2W);
    for (int i = i0; i < QKVN*DIMC/2;   i += stride) dq[i] = __float22half2_rn(q2[i]);
    for (int i = i0; i < DIMC*DIMC/2;   i += stride) dp[i] = __float22half2_rn(p2[i]);
    for (int i = i0; i < HIDDEN*DIMC/2; i += stride) df[i] = __float22half2_rn(f2[i]);
    for (int i = i0; i < DIMC*HIDDEN/2; i += stride) dg[i] = __float22half2_rn(g2[i]);
}

// ---------------- LayerNorm: 1 warp per token ----------------
__global__ void __launch_bounds__(256) ln_fast(
    const float* __restrict__ px, const float* __restrict__ py,
    const float* __restrict__ w,  const float* __restrict__ bsh,
    __half* __restrict__ out)
{
    int wi = threadIdx.x >> 5, lane = threadIdx.x & 31;
    int t  = blockIdx.x*8 + wi;
    int bb = t / MTOK, pos = t - bb*MTOK;
    const float* src = (pos < NX)
        ? px + (size_t)(bb*NX + pos)*DIMC
        : py + (size_t)(bb*NY + pos - NX)*DIMC;

    float4 v[3];
    float s = 0.f, sq = 0.f;
    #pragma unroll
    for (int i = 0; i < 3; i++) {
        v[i] = ((const float4*)src)[lane + 32*i];
        s  += v[i].x + v[i].y + v[i].z + v[i].w;
        sq += v[i].x*v[i].x + v[i].y*v[i].y + v[i].z*v[i].z + v[i].w*v[i].w;
    }
    #pragma unroll
    for (int o = 16; o; o >>= 1) {
        s  += __shfl_xor_sync(0xffffffffu, s,  o);
        sq += __shfl_xor_sync(0xffffffffu, sq, o);
    }
    float mean = s * (1.0f/DIMC);
    float inv  = rsqrtf(sq * (1.0f/DIMC) - mean*mean + LN_EPS);

    uint32_t* op = (uint32_t*)(out + (size_t)t*DIMC);
    #pragma unroll
    for (int i = 0; i < 3; i++) {
        int idx4 = lane + 32*i;
        float4 ww = ((const float4*)w)[idx4];
        float4 bb4 = ((const float4*)bsh)[idx4];
        op[2*idx4]   = pack_h2((v[i].x-mean)*inv*ww.x + bb4.x, (v[i].y-mean)*inv*ww.y + bb4.y);
        op[2*idx4+1] = pack_h2((v[i].z-mean)*inv*ww.z + bb4.z, (v[i].w-mean)*inv*ww.w + bb4.w);
    }
}

// ---------------- pairwise epilogue for fp32-residual outputs ----------------
template<int EPI>
__device__ __forceinline__ void epi_res2(int m, int n, float v0, float v1,
    const float* __restrict__ bias,
    const float* __restrict__ resx, const float* __restrict__ resy,
    float* __restrict__ outx, float* __restrict__ outy)
{
    float2 bv = *(const float2*)(bias + n);
    int bb  = m / MTOK;
    int pos = m - bb * MTOK;
    size_t idx;
    float* outp;
    const float* resp;
    if (pos < NX) {
        idx = ((size_t)(bb*NX + pos))*DIMC + n;
        outp = outx;
        resp = (EPI == 1) ? resx : outx;
    } else {
        idx = ((size_t)(bb*NY + pos - NX))*DIMC + n;
        outp = outy;
        resp = (EPI == 1) ? resy : outy;
    }
    float2 r = *(const float2*)(resp + idx);
    float2 o = make_float2(v0 + bv.x + r.x, v1 + bv.y + r.y);
    *(float2*)(outp + idx) = o;
}

// ---------------- raw-PTX fp16 GEMM: 3-stage pipeline, ldmatrix, register epilogue ----------------
template<int EPI>
__global__ void __launch_bounds__(256, 2) gemm_raw(
    const __half* __restrict__ A, const __half* __restrict__ W,
    const float* __restrict__ bias, __half* __restrict__ C,
    int M, int N, int K,
    const float* __restrict__ resx, const float* __restrict__ resy,
    float* __restrict__ outx, float* __restrict__ outy)
{
    extern __shared__ __align__(16) char dsm[];
    __half* Abuf = (__half*)dsm;                    // 3 x GT_BYTES
    __half* Wbuf = (__half*)(dsm + 3*GT_BYTES);     // 3 x GT_BYTES

    int tid = threadIdx.x;
    int w = tid >> 5, lane = tid & 31;
    int g = lane >> 2, t = lane & 3;
    int wm = w >> 1, wn = w & 1;
    int m0 = blockIdx.y << 7;
    int n0 = blockIdx.x << 7;

    int seg = lane >> 3, r7 = lane & 7;
    uint32_t aBase = (uint32_t)__cvta_generic_to_shared(Abuf) +
        (uint32_t)((wm*32 + r7 + ((seg & 1) << 3))*144 + ((seg >> 1) << 4));
    uint32_t bBase = (uint32_t)__cvta_generic_to_shared(Wbuf) +
        (uint32_t)((wn*64 + r7 + ((seg & 2) << 2))*144 + ((seg & 1) << 4));

    int srow = tid >> 3, sc8 = (tid & 7) << 3;

    float acc[2][8][4];
    #pragma unroll
    for (int i = 0; i < 2; i++)
        #pragma unroll
        for (int j = 0; j < 8; j++)
            #pragma unroll
            for (int c = 0; c < 4; c++) acc[i][j][c] = 0.f;

    int T = K >> 6;
    #pragma unroll
    for (int p = 0; p < 2; p++) {
        __half* Ad = Abuf + p*(GT_BYTES/2);
        __half* Wd = Wbuf + p*(GT_BYTES/2);
        int k0 = p << 6;
        #pragma unroll
        for (int i = 0; i < 4; i++) {
            int row = srow + i*32;
            cp16(Ad + row*HTS + sc8, A + (size_t)(m0+row)*K + k0 + sc8);
            cp16(Wd + row*HTS + sc8, W + (size_t)(n0+row)*K + k0 + sc8);
        }
        CP_COMMIT();
    }

    for (int tt = 0; tt < T; tt++) {
        if (tt < T-1) { CP_WAIT1(); } else { CP_WAIT0(); }
        __syncthreads();
        if (tt + 2 < T) {
            int bi = (tt+2) % 3;
            __half* Ad = Abuf + bi*(GT_BYTES/2);
            __half* Wd = Wbuf + bi*(GT_BYTES/2);
            int k0 = (tt+2) << 6;
            #pragma unroll
            for (int i = 0; i < 4; i++) {
                int row = srow + i*32;
                cp16(Ad + row*HTS + sc8, A + (size_t)(m0+row)*K + k0 + sc8);
                cp16(Wd + row*HTS + sc8, W + (size_t)(n0+row)*K + k0 + sc8);
            }
            CP_COMMIT();
        }
        int cb = tt % 3;
        uint32_t aB = aBase + cb*GT_BYTES;
        uint32_t bB = bBase + cb*GT_BYTES;

        #pragma unroll
        for (int ks = 0; ks < 4; ks++) {
            uint32_t a0[4], a1[4];
            ldsm4(a0[0], a0[1], a0[2], a0[3], aB + 32*ks);
            ldsm4(a1[0], a1[1], a1[2], a1[3], aB + 16*144 + 32*ks);
            #pragma unroll
            for (int bi = 0; bi < 4; bi++) {
                uint32_t p0, p1, q0, q1;
                ldsm4(p0, p1, q0, q1, bB + (16*bi)*144 + 32*ks);
                mma16816(acc[0][2*bi],   a0, p0, p1);
                mma16816(acc[1][2*bi],   a1, p0, p1);
                mma16816(acc[0][2*bi+1], a0, q0, q1);
                mma16816(acc[1][2*bi+1], a1, q0, q1);
            }
        }
    }

    #pragma unroll
    for (int i = 0; i < 2; i++) {
        int row0 = m0 + wm*32 + i*16 + g;
        int row1 = row0 + 8;
        #pragma unroll
        for (int j = 0; j < 8; j++) {
            int col = n0 + wn*64 + j*8 + 2*t;
            float c0 = acc[i][j][0], c1 = acc[i][j][1];
            float c2 = acc[i][j][2], c3 = acc[i][j][3];
            if (EPI == 0) {
                *(uint32_t*)(C + (size_t)row0*N + col) = pack_h2(c0, c1);
                *(uint32_t*)(C + (size_t)row1*N + col) = pack_h2(c2, c3);
            } else if (EPI == 2) {
                float2 bv = *(const float2*)(bias + col);
                *(uint32_t*)(C + (size_t)row0*N + col) =
                    pack_h2(gelu_erf(c0 + bv.x), gelu_erf(c1 + bv.y));
                *(uint32_t*)(C + (size_t)row1*N + col) =
                    pack_h2(gelu_erf(c2 + bv.x), gelu_erf(c3 + bv.y));
            } else {
                epi_res2<EPI>(row0, col, c0, c1, bias, resx, resy, outx, outy);
                epi_res2<EPI>(row1, col, c2, c3, bias, resx, resy, outx, outy);
            }
        }
    }
}

// ---------------- unified attention v8: f16x2 exp, tensor-pipe row sums ----------------
// blockIdx.x in [0,16): self q-block, klen=2048, direct fp16 output.
// blockIdx.x in [16,24): cross item, split-K x4, partials.
__global__ void __launch_bounds__(256, 2) attn_v8(
    const __half* __restrict__ qkvh, __half* __restrict__ attno,
    float* __restrict__ pO, float* __restrict__ pL)
{
    extern __shared__ __align__(16) char dsm[];
    __half* Kb[2] = { (__half*)(dsm),              (__half*)(dsm + KV_BYTES)   };
    __half* Vb[2] = { (__half*)(dsm + 2*KV_BYTES), (__half*)(dsm + 3*KV_BYTES) };

    int tid = threadIdx.x, w = tid >> 5, lane = tid & 31;
    int g = lane >> 2, t = lane & 3;
    int h = blockIdx.y, b = blockIdx.z;

    int item = blockIdx.x;
    bool self = (item < SQB);
    int qb, sp, q0, koff, klen;
    if (self) {
        qb = item; sp = 0;
        q0 = qb << 7;
        koff = 0; klen = NX;
    } else {
        int c = item - SQB;
        qb = c >> 2; sp = c & 3;
        q0 = NX + (qb << 7);
        klen = KSPLIT; koff = sp * KSPLIT;
    }

    int seg = lane >> 3, r7 = lane & 7;
    uint32_t kBase = (uint32_t)__cvta_generic_to_shared(Kb[0]) +
        (uint32_t)((r7 + ((seg & 2) << 2))*144 + ((seg & 1) << 4));

    uint32_t qa[4][4];
    {
        const __half* qrow0 = qkvh + (size_t)(b*MTOK + q0 + w*16 + g)*QKVN + h*HD;
        const __half* qrow1 = qrow0 + 8*QKVN;
        #pragma unroll
        for (int c = 0; c < 4; c++) {
            qa[c][0] = *(const uint32_t*)(qrow0 + 16*c     + 2*t);
            qa[c][1] = *(const uint32_t*)(qrow1 + 16*c     + 2*t);
            qa[c][2] = *(const uint32_t*)(qrow0 + 16*c + 8 + 2*t);
            qa[c][3] = *(const uint32_t*)(qrow1 + 16*c + 8 + 2*t);
        }
    }

    float oac[8][4];
    #pragma unroll
    for (int j = 0; j < 8; j++)
        #pragma unroll
        for (int c = 0; c < 4; c++) oac[j][c] = 0.f;
    float osum[4] = {0.f, 0.f, 0.f, 0.f};           // row-sum accumulator (ones-column mma)
    const uint32_t ones = (g == 0) ? 0x3C003C00u : 0u;  // B frag: col 0 of n8 tile = 1.0

    const __half* kbase = qkvh + ((size_t)b*MTOK)*QKVN + DIMC   + h*HD;
    const __half* vbase = qkvh + ((size_t)b*MTOK)*QKVN + 2*DIMC + h*HD;

    int T = klen >> 6;
    {
        #pragma unroll
        for (int i = 0; i < 2; i++) {
            int idx = tid + i*256;
            int row = idx >> 3, c8 = (idx & 7) << 3;
            cp16(Kb[0] + row*HTS + c8, kbase + (size_t)(koff+row)*QKVN + c8);
            cp16(Vb[0] + row*HTS + c8, vbase + (size_t)(koff+row)*QKVN + c8);
        }
        CP_COMMIT();
    }

    for (int it = 0; it < T; it++) {
        CP_WAIT0();
        __syncthreads();
        if (it + 1 < T) {
            int kt = koff + ((it+1) << 6);
            __half* Kn = Kb[(it+1)&1];
            __half* Vn = Vb[(it+1)&1];
            #pragma unroll
            for (int i = 0; i < 2; i++) {
                int idx = tid + i*256;
                int row = idx >> 3, c8 = (idx & 7) << 3;
                cp16(Kn + row*HTS + c8, kbase + (size_t)(kt+row)*QKVN + c8);
                cp16(Vn + row*HTS + c8, vbase + (size_t)(kt+row)*QKVN + c8);
            }
            CP_COMMIT();
        }
        uint32_t kB = kBase + (it&1)*KV_BYTES;
        __half* Vs = Vb[it&1];

        // S = Q @ K^T ; P = exp2(S * c) via f16x2 MUFU (2 values per op)
        uint32_t ph[8][2];
        #pragma unroll
        for (int jp = 0; jp < 4; jp++) {
            float s0[4] = {0.f,0.f,0.f,0.f};
            float s1[4] = {0.f,0.f,0.f,0.f};
            #pragma unroll
            for (int c = 0; c < 4; c++) {
                uint32_t p0, p1, q0r, q1r;
                ldsm4(p0, p1, q0r, q1r, kB + (16*jp)*144 + 32*c);
                mma16816(s0, qa[c], p0, p1);
                mma16816(s1, qa[c], q0r, q1r);
            }
            ph[2*jp][0]   = h2exp2(pack_h2(s0[0]*SC_LOG2E, s0[1]*SC_LOG2E));
            ph[2*jp][1]   = h2exp2(pack_h2(s0[2]*SC_LOG2E, s0[3]*SC_LOG2E));
            ph[2*jp+1][0] = h2exp2(pack_h2(s1[0]*SC_LOG2E, s1[1]*SC_LOG2E));
            ph[2*jp+1][1] = h2exp2(pack_h2(s1[2]*SC_LOG2E, s1[3]*SC_LOG2E));
        }

        // O += P @ V ; row sums via ones-column mma on tensor pipe
        #pragma unroll
        for (int kc = 0; kc < 4; kc++) {
            uint32_t af[4] = { ph[2*kc][0], ph[2*kc][1], ph[2*kc+1][0], ph[2*kc+1][1] };
            mma16816(osum, af, ones, ones);
            #pragma unroll
            for (int jd = 0; jd < 8; jd += 2) {
                int row = 16*kc + ((lane >> 3) & 1)*8 + (lane & 7);
                int col = 8*jd + ((lane >> 4) << 3);
                uint32_t addr = (uint32_t)__cvta_generic_to_shared(Vs + row*HTS + col);
                uint32_t v0, v1, v2, v3;
                asm volatile(
                    "ldmatrix.sync.aligned.m8n8.x4.trans.shared.b16 {%0,%1,%2,%3}, [%4];"
                    : "=r"(v0), "=r"(v1), "=r"(v2), "=r"(v3) : "r"(addr));
                mma16816(oac[jd],   af, v0, v1);
                mma16816(oac[jd+1], af, v2, v3);
            }
        }
    }

    // broadcast row sums from the t==0 lane of each quad
    float rs0 = __shfl_sync(0xffffffffu, osum[0], lane & 28);
    float rs1 = __shfl_sync(0xffffffffu, osum[2], lane & 28);

    if (!self) {
        int pidx = ((b*HEADS + h)*QBY + qb)*NSPLIT + sp;
        float* dst0 = pO + (size_t)pidx*(128*64) + (w*16 + g)*64;
        float* dst1 = dst0 + 8*64;
        #pragma unroll
        for (int jd = 0; jd < 8; jd++) {
            int col = 8*jd + 2*t;
            *(float2*)(dst0 + col) = make_float2(oac[jd][0], oac[jd][1]);
            *(float2*)(dst1 + col) = make_float2(oac[jd][2], oac[jd][3]);
        }
        if (t == 0) {
            pL[pidx*128 + w*16 + g]     = rs0;
            pL[pidx*128 + w*16 + g + 8] = rs1;
        }
    } else {
        float inv0 = 1.f / rs0;
        float inv1 = 1.f / rs1;
        __half* orow0 = attno + (size_t)(b*MTOK + q0 + w*16 + g)*DIMC + h*HD;
        __half* orow1 = orow0 + 8*DIMC;
        #pragma unroll
        for (int jd = 0; jd < 8; jd++) {
            int col = 8*jd + 2*t;
            *(uint32_t*)(orow0 + col) = pack_h2(oac[jd][0]*inv0, oac[jd][1]*inv0);
            *(uint32_t*)(orow1 + col) = pack_h2(oac[jd][2]*inv1, oac[jd][3]*inv1);
        }
    }
}

// ---------------- merge split-K partials (cross only) ----------------
__global__ void __launch_bounds__(128) merge_attn(
    const float* __restrict__ pO, const float* __restrict__ pL,
    __half* __restrict__ attno)
{
    int qb = blockIdx.x, h = blockIdx.y, b = blockIdx.z;
    int r = threadIdx.x;
    int base = ((b*HEADS + h)*QBY + qb)*NSPLIT;

    float L = 0.f;
    #pragma unroll
    for (int s = 0; s < NSPLIT; s++) L += pL[(base+s)*128 + r];
    float inv = 1.f / L;

    int qi = NX + (qb << 7) + r;
    __half* op = attno + ((size_t)(b*MTOK + qi))*DIMC + h*HD;
    #pragma unroll 4
    for (int c = 0; c < 64; c++) {
        float o = 0.f;
        #pragma unroll
        for (int s = 0; s < NSPLIT; s++)
            o += pO[(size_t)(base+s)*(128*64) + r*64 + c];
        op[c] = __float2half(o * inv);
    }
}

// ---------------- launch ----------------
extern "C" void kernel_launch(void* const* d_in, const int* in_sizes, int n_in,
                              void* d_out, int out_size)
{
    const float* x     = (const float*)d_in[0];
    const float* y     = (const float*)d_in[1];
    const float* n1w   = (const float*)d_in[2];
    const float* n1b   = (const float*)d_in[3];
    const float* n2w   = (const float*)d_in[4];
    const float* n2b   = (const float*)d_in[5];
    const float* qkvw  = (const float*)d_in[6];
    const float* projw = (const float*)d_in[7];
    const float* projb = (const float*)d_in[8];
    const float* fc1w  = (const float*)d_in[9];
    const float* fc1bb = (const float*)d_in[10];
    const float* fc2w  = (const float*)d_in[11];
    const float* fc2b  = (const float*)d_in[12];
    (void)in_sizes; (void)n_in; (void)out_size;

    float* outx = (float*)d_out;
    float* outy = outx + (size_t)BATCH*NX*DIMC;

    __half *catln, *qkvh, *attno, *ln2o, *fc1o, *wrnd;
    float *pO, *pL;
    cudaGetSymbolAddress((void**)&catln, g_catln);
    cudaGetSymbolAddress((void**)&qkvh,  g_qkvh);
    cudaGetSymbolAddress((void**)&attno, g_attno);
    cudaGetSymbolAddress((void**)&ln2o,  g_ln2);
    cudaGetSymbolAddress((void**)&fc1o,  g_fc1);
    cudaGetSymbolAddress((void**)&wrnd,  g_wrnd);
    cudaGetSymbolAddress((void**)&pO,    g_pO);
    cudaGetSymbolAddress((void**)&pL,    g_pL);

    cudaFuncSetAttribute(gemm_raw<0>, cudaFuncAttributeMaxDynamicSharedMemorySize, SMEM_GEMM);
    cudaFuncSetAttribute(gemm_raw<1>, cudaFuncAttributeMaxDynamicSharedMemorySize, SMEM_GEMM);
    cudaFuncSetAttribute(gemm_raw<2>, cudaFuncAttributeMaxDynamicSharedMemorySize, SMEM_GEMM);
    cudaFuncSetAttribute(gemm_raw<3>, cudaFuncAttributeMaxDynamicSharedMemorySize, SMEM_GEMM);
    cudaFuncSetAttribute(attn_v8,     cudaFuncAttributeMaxDynamicSharedMemorySize, SMEM_ATTN5);

    // 0) pre-round weights to fp16
    round_weights<<<256, 256>>>(qkvw, projw, fc1w, fc2w, wrnd);
    // 1) LN1 over concat(x, y)
    ln_fast<<<TTOK/8, 256>>>(x, y, n1w, n1b, catln);
    // 2) fused QKV GEMM
    gemm_raw<0><<<dim3(QKVN/128, TTOK/128), 256, SMEM_GEMM>>>(catln, wrnd + OFF_QKVW, nullptr, qkvh,
        TTOK, QKVN, DIMC, nullptr, nullptr, nullptr, nullptr);
    // 3) ALL attention in one launch (self direct + cross split-K)
    attn_v8<<<dim3(AITEMS, HEADS, BATCH), 256, SMEM_ATTN5>>>(qkvh, attno, pO, pL);
    // 4) merge cross partials
    merge_attn<<<dim3(QBY, HEADS, BATCH), 128>>>(pO, pL, attno);
    // 5) output projection + bias + input residual -> d_out
    gemm_raw<1><<<dim3(DIMC/128, TTOK/128), 256, SMEM_GEMM>>>(attno, wrnd + OFF_PROJW, projb, nullptr,
        TTOK, DIMC, DIMC, x, y, outx, outy);
    // 6) LN2 over d_out
    ln_fast<<<TTOK/8, 256>>>(outx, outy, n2w, n2b, ln2o);
    // 7) fc1 + bias + exact GELU
    gemm_raw<2><<<dim3(HIDDEN/128, TTOK/128), 256, SMEM_GEMM>>>(ln2o, wrnd + OFF_FC1W, fc1bb, fc1o,
        TTOK, HIDDEN, DIMC, nullptr, nullptr, nullptr, nullptr);
    // 8) fc2 + bias + residual (in place on d_out)
    gemm_raw<3><<<dim3(DIMC/128, TTOK/128), 256, SMEM_GEMM>>>(fc1o, wrnd + OFF_FC2W, fc2b, nullptr,
        TTOK, DIMC, HIDDEN, nullptr, nullptr, outx, outy);
}